// round 4
// baseline (speedup 1.0000x reference)
#include <cuda_runtime.h>
#include <math.h>
#include <stdint.h>

#define BATCH 8
#define NPIX 4096
#define CCH 64
#define HID 128
#define K3 576
#define ATT_SCALE 0.25f

static __device__ float g_Weff[K3 * HID];
static __device__ float g_beff[HID];
static __device__ float g_xbuf[2][BATCH * NPIX * CCH];
static __device__ float g_hd[BATCH * NPIX * HID];
static __device__ float g_part[256 * 2];
static __device__ float g_stats[BATCH * 2];
static __device__ float g_q[BATCH * NPIX * CCH];
static __device__ float g_k[BATCH * NPIX * CCH];
static __device__ float g_v[BATCH * NPIX * CCH];
static __device__ float g_t[BATCH * NPIX * CCH];
static __device__ int g_maskmode;

__global__ void k_maskdetect(const unsigned char* m, int nbytes) {
    __shared__ int hasBig, hasMis;
    if (threadIdx.x == 0) { hasBig = 0; hasMis = 0; }
    __syncthreads();
    for (int i = threadIdx.x; i < nbytes; i += blockDim.x) {
        unsigned char v = m[i];
        if (v > 1) hasBig = 1;
        else if (v && (i & 3)) hasMis = 1;
    }
    __syncthreads();
    if (threadIdx.x == 0) g_maskmode = (!hasBig && hasMis) ? 1 : 0;
}

__global__ void k_fold(const float* __restrict__ fc0_w, const float* __restrict__ fc0_b,
                       const float* __restrict__ p0_w, const float* __restrict__ p0_b,
                       const float* __restrict__ p1_w, const float* __restrict__ p1_b) {
    int t = blockIdx.x * 256 + threadIdx.x;
    if (t >= HID * K3) return;
    int o = t / K3, k = t - o * K3;
    int tap = k >> 6, c = k & 63;
    const float* f1 = fc0_w + o * 192 + 64;
    const float* f2 = fc0_w + o * 192 + 128;
    float acc = 0.f;
    for (int m = 0; m < 64; m++) {
        acc = fmaf(f1[m], p0_w[(m * 64 + c) * 9 + tap], acc);
        acc = fmaf(f2[m], p1_w[(m * 64 + c) * 9 + tap], acc);
    }
    if (tap == 4) acc += fc0_w[o * 192 + c];
    g_Weff[k * HID + o] = acc;
    if (k == 0) {
        float b = fc0_b[o];
        for (int m = 0; m < 64; m++) {
            b = fmaf(f1[m], p0_b[m], b);
            b = fmaf(f2[m], p1_b[m], b);
        }
        g_beff[o] = b;
    }
}

__device__ __forceinline__ int refl(int v) { return v < 0 ? -v : (v > 63 ? 126 - v : v); }

__global__ void __launch_bounds__(256) k_conv(const float* __restrict__ xin) {
    __shared__ float Wsh[32 * 128];
    __shared__ float Xsh[32 * 132];
    __shared__ float red[512];
    int tid = threadIdx.x;
    int batch = blockIdx.x >> 5;
    int y0 = (blockIdx.x & 31) << 1;
    int tx = tid & 15, ty = tid >> 4;
    const float* xb = xin + (size_t)batch * NPIX * CCH;
    float acc[8][8];
    #pragma unroll
    for (int i = 0; i < 8; i++)
        #pragma unroll
        for (int j = 0; j < 8; j++) acc[i][j] = 0.f;

    for (int kc = 0; kc < 18; kc++) {
        int tap = kc >> 1;
        int c0 = (kc & 1) << 5;
        int dy = tap / 3 - 1, dx = tap % 3 - 1;
        #pragma unroll
        for (int i = 0; i < 16; i++) {
            int lin = tid + i * 256;
            Wsh[lin] = g_Weff[(kc * 32 + (lin >> 7)) * HID + (lin & 127)];
        }
        #pragma unroll
        for (int i = 0; i < 16; i++) {
            int lin = tid + i * 256;
            int p = lin >> 5, kk = lin & 31;
            int ry = refl(y0 + (p >> 6) + dy), rx = refl((p & 63) + dx);
            Xsh[kk * 132 + p] = xb[(ry * 64 + rx) * CCH + c0 + kk];
        }
        __syncthreads();
        #pragma unroll 4
        for (int kk = 0; kk < 32; kk++) {
            float4 wa0 = *(const float4*)&Wsh[kk * 128 + (tx << 2)];
            float4 wa1 = *(const float4*)&Wsh[kk * 128 + 64 + (tx << 2)];
            float4 xa0 = *(const float4*)&Xsh[kk * 132 + (ty << 2)];
            float4 xa1 = *(const float4*)&Xsh[kk * 132 + 64 + (ty << 2)];
            float a[8] = {wa0.x, wa0.y, wa0.z, wa0.w, wa1.x, wa1.y, wa1.z, wa1.w};
            float b[8] = {xa0.x, xa0.y, xa0.z, xa0.w, xa1.x, xa1.y, xa1.z, xa1.w};
            #pragma unroll
            for (int i = 0; i < 8; i++)
                #pragma unroll
                for (int j = 0; j < 8; j++) acc[i][j] = fmaf(a[i], b[j], acc[i][j]);
        }
        __syncthreads();
    }
    float s = 0.f, sq = 0.f;
    #pragma unroll
    for (int j = 0; j < 8; j++) {
        int p = (j < 4) ? (ty * 4 + j) : (64 + ty * 4 + (j - 4));
        size_t rowbase = ((size_t)batch * NPIX + y0 * 64 + p) * HID;
        #pragma unroll
        for (int half = 0; half < 2; half++) {
            int o = half * 64 + (tx << 2);
            float r0 = fmaxf(acc[half * 4 + 0][j] + g_beff[o + 0], 0.f);
            float r1 = fmaxf(acc[half * 4 + 1][j] + g_beff[o + 1], 0.f);
            float r2 = fmaxf(acc[half * 4 + 2][j] + g_beff[o + 2], 0.f);
            float r3 = fmaxf(acc[half * 4 + 3][j] + g_beff[o + 3], 0.f);
            float4 v4 = {r0, r1, r2, r3};
            *(float4*)&g_hd[rowbase + o] = v4;
            s += r0 + r1 + r2 + r3;
            sq += r0 * r0 + r1 * r1 + r2 * r2 + r3 * r3;
        }
    }
    red[tid] = s; red[256 + tid] = sq;
    __syncthreads();
    for (int st = 128; st > 0; st >>= 1) {
        if (tid < st) { red[tid] += red[tid + st]; red[256 + tid] += red[256 + tid + st]; }
        __syncthreads();
    }
    if (tid == 0) { g_part[blockIdx.x * 2] = red[0]; g_part[blockIdx.x * 2 + 1] = red[256]; }
}

__global__ void k_stats() {
    int b = blockIdx.x, lane = threadIdx.x;
    float s = g_part[(b * 32 + lane) * 2];
    float sq = g_part[(b * 32 + lane) * 2 + 1];
    #pragma unroll
    for (int o = 16; o > 0; o >>= 1) {
        s += __shfl_xor_sync(0xffffffffu, s, o);
        sq += __shfl_xor_sync(0xffffffffu, sq, o);
    }
    if (lane == 0) {
        const float inv = 1.f / 524288.f;
        float mu = s * inv;
        g_stats[b * 2] = mu;
        g_stats[b * 2 + 1] = rsqrtf(sq * inv - mu * mu + 1e-5f);
    }
}

__global__ void __launch_bounds__(128) k_fc1(const float* __restrict__ xin,
                                             const float* __restrict__ nw, const float* __restrict__ nb,
                                             const float* __restrict__ fc1_w,
                                             const void* __restrict__ mask, int s,
                                             float* __restrict__ xout) {
    __shared__ float ysh[32 * 128];
    __shared__ float Wsh[64 * 65];
    int tid = threadIdx.x;
    int b = blockIdx.x >> 7;
    int p0 = (blockIdx.x & 127) << 5;
    float mu = g_stats[b * 2], rs = g_stats[b * 2 + 1];
    #pragma unroll
    for (int i = 0; i < 32; i++) {
        int lin = tid + i * 128;
        size_t gi = ((size_t)b * NPIX + p0) * HID + lin;
        int ii = p0 * HID + lin;
        ysh[lin] = (g_hd[gi] - mu) * rs * nw[ii] + nb[ii];
    }
    int cg = tid & 15, pg = tid >> 4;
    int cbase = cg * 4, pbase = pg * 4;
    float acc[4][4] = {};
    for (int hc = 0; hc < 128; hc += 64) {
        __syncthreads();
        #pragma unroll
        for (int i = 0; i < 32; i++) {
            int lin = tid + i * 128;
            Wsh[(lin & 63) * 65 + (lin >> 6)] = fc1_w[(lin >> 6) * 128 + hc + (lin & 63)];
        }
        __syncthreads();
        #pragma unroll 4
        for (int h = 0; h < 64; h++) {
            float w0 = Wsh[h * 65 + cbase + 0];
            float w1 = Wsh[h * 65 + cbase + 1];
            float w2 = Wsh[h * 65 + cbase + 2];
            float w3 = Wsh[h * 65 + cbase + 3];
            #pragma unroll
            for (int pp = 0; pp < 4; pp++) {
                float y = ysh[(pbase + pp) * 128 + hc + h];
                acc[0][pp] = fmaf(w0, y, acc[0][pp]);
                acc[1][pp] = fmaf(w1, y, acc[1][pp]);
                acc[2][pp] = fmaf(w2, y, acc[2][pp]);
                acc[3][pp] = fmaf(w3, y, acc[3][pp]);
            }
        }
    }
    int mode = g_maskmode;
    #pragma unroll
    for (int pp = 0; pp < 4; pp++) {
        size_t gp = (size_t)b * NPIX + p0 + pbase + pp;
        size_t mi = (size_t)s * 32768 + gp;
        float mv;
        if (mode) mv = ((const unsigned char*)mask)[mi] ? 1.f : 0.f;
        else mv = ((const unsigned int*)mask)[mi] ? 1.f : 0.f;
        #pragma unroll
        for (int cc = 0; cc < 4; cc++) {
            int c = cbase + cc;
            xout[gp * CCH + c] = xin[gp * CCH + c] + acc[cc][pp] * mv;
        }
    }
}

__global__ void __launch_bounds__(128) k_qkv(const float* __restrict__ xin,
                                             const float* __restrict__ lw, const float* __restrict__ lb,
                                             const float* __restrict__ qkvw) {
    __shared__ float ysh[32 * 64];
    __shared__ float Wsh[64 * 65];
    int tid = threadIdx.x;
    int b = blockIdx.x >> 7;
    int p0 = (blockIdx.x & 127) << 5;
    int warp = tid >> 5, lane = tid & 31;
    #pragma unroll
    for (int k = 0; k < 8; k++) {
        int pix = warp * 8 + k;
        size_t base = ((size_t)b * NPIX + p0 + pix) * CCH;
        float v0 = xin[base + lane], v1 = xin[base + lane + 32];
        float s = v0 + v1, sq = v0 * v0 + v1 * v1;
        #pragma unroll
        for (int o = 16; o > 0; o >>= 1) {
            s += __shfl_xor_sync(0xffffffffu, s, o);
            sq += __shfl_xor_sync(0xffffffffu, sq, o);
        }
        float mu = s * (1.f / 64.f);
        float rsg = rsqrtf(sq * (1.f / 64.f) - mu * mu + 1e-5f);
        ysh[pix * 64 + lane] = (v0 - mu) * rsg * lw[lane] + lb[lane];
        ysh[pix * 64 + lane + 32] = (v1 - mu) * rsg * lw[lane + 32] + lb[lane + 32];
    }
    int cg = tid & 15, pg = tid >> 4;
    int obase = cg * 4, pbase = pg * 4;
    float* outs[3] = {g_q, g_k, g_v};
    for (int ch = 0; ch < 3; ch++) {
        __syncthreads();
        #pragma unroll
        for (int i = 0; i < 32; i++) {
            int lin = tid + i * 128;
            Wsh[(lin & 63) * 65 + (lin >> 6)] = qkvw[(ch * 64 + (lin >> 6)) * 64 + (lin & 63)];
        }
        __syncthreads();
        float acc[4][4] = {};
        #pragma unroll 4
        for (int k = 0; k < 64; k++) {
            float w0 = Wsh[k * 65 + obase + 0];
            float w1 = Wsh[k * 65 + obase + 1];
            float w2 = Wsh[k * 65 + obase + 2];
            float w3 = Wsh[k * 65 + obase + 3];
            #pragma unroll
            for (int pp = 0; pp < 4; pp++) {
                float y = ysh[(pbase + pp) * 64 + k];
                acc[0][pp] = fmaf(w0, y, acc[0][pp]);
                acc[1][pp] = fmaf(w1, y, acc[1][pp]);
                acc[2][pp] = fmaf(w2, y, acc[2][pp]);
                acc[3][pp] = fmaf(w3, y, acc[3][pp]);
            }
        }
        float* op = outs[ch];
        #pragma unroll
        for (int pp = 0; pp < 4; pp++) {
            size_t base = ((size_t)b * NPIX + p0 + pbase + pp) * CCH;
            #pragma unroll
            for (int cc = 0; cc < 4; cc++) op[base + obase + cc] = acc[cc][pp];
        }
    }
}

__global__ void __launch_bounds__(128) k_attn(const float* __restrict__ xn,
                                              const float* __restrict__ outw,
                                              const float* __restrict__ outb) {
    __shared__ float sm[64 * 61 * 2 + 32 * 65];
    float* ksh = sm;
    float* vsh = sm + 64 * 61;
    float* osh = sm + 64 * 61 * 2;
    int tid = threadIdx.x;
    int b = blockIdx.x >> 7;
    int tile = blockIdx.x & 127;
    int tx0 = (tile & 7) << 3;
    int ty0 = (tile >> 3) << 2;
    #pragma unroll
    for (int i = 0; i < 30; i++) {
        int lin = tid + i * 128;
        int pos = lin >> 6, ch = lin & 63;
        int hy = pos / 10, hx = pos - hy * 10;
        int gy = ty0 + hy - 1, gx = tx0 + hx - 1;
        float kv = 0.f, vv = 0.f;
        if ((unsigned)gy < 64u && (unsigned)gx < 64u) {
            size_t a = ((size_t)b * NPIX + gy * 64 + gx) * CCH + ch;
            kv = g_k[a]; vv = g_v[a];
        }
        ksh[ch * 61 + pos] = kv;
        vsh[ch * 61 + pos] = vv;
    }
    __syncthreads();
    {
        int head = tid >> 5, lp = tid & 31;
        int py = lp >> 3, px = lp & 7;
        int gy = ty0 + py, gx = tx0 + px;
        size_t qbase = ((size_t)b * NPIX + gy * 64 + gx) * CCH + head * 16;
        float q[16];
        #pragma unroll
        for (int i = 0; i < 4; i++) {
            float4 t4 = *(const float4*)&g_q[qbase + i * 4];
            q[i * 4] = t4.x; q[i * 4 + 1] = t4.y; q[i * 4 + 2] = t4.z; q[i * 4 + 3] = t4.w;
        }
        float lg[9];
        #pragma unroll
        for (int t = 0; t < 9; t++) {
            int pos = (py + t / 3) * 10 + px + t % 3;
            float d = 0.f;
            #pragma unroll
            for (int i = 0; i < 16; i++) d = fmaf(q[i], ksh[(head * 16 + i) * 61 + pos], d);
            lg[t] = d * ATT_SCALE;
        }
        float m = lg[0];
        #pragma unroll
        for (int t = 1; t < 9; t++) m = fmaxf(m, lg[t]);
        float e[9], ssum = 0.f;
        #pragma unroll
        for (int t = 0; t < 9; t++) { e[t] = __expf(lg[t] - m); ssum += e[t]; }
        float inv = 1.f / ssum;
        float o[16] = {};
        #pragma unroll
        for (int t = 0; t < 9; t++) {
            int pos = (py + t / 3) * 10 + px + t % 3;
            float a = e[t] * inv;
            #pragma unroll
            for (int i = 0; i < 16; i++) o[i] = fmaf(a, vsh[(head * 16 + i) * 61 + pos], o[i]);
        }
        #pragma unroll
        for (int i = 0; i < 16; i++) osh[lp * 65 + head * 16 + i] = o[i];
    }
    __syncthreads();
    float* wsh = sm;
    #pragma unroll
    for (int i = 0; i < 32; i++) {
        int lin = tid + i * 128;
        wsh[(lin & 63) * 65 + (lin >> 6)] = outw[(lin >> 6) * 64 + (lin & 63)];
    }
    __syncthreads();
    int cg = tid & 15, pg = tid >> 4;
    int cbase = cg * 4, pbase = pg * 4;
    float acc[4][4] = {};
    #pragma unroll 4
    for (int k = 0; k < 64; k++) {
        float w0 = wsh[k * 65 + cbase + 0];
        float w1 = wsh[k * 65 + cbase + 1];
        float w2 = wsh[k * 65 + cbase + 2];
        float w3 = wsh[k * 65 + cbase + 3];
        #pragma unroll
        for (int pp = 0; pp < 4; pp++) {
            float ov = osh[(pbase + pp) * 65 + k];
            acc[0][pp] = fmaf(w0, ov, acc[0][pp]);
            acc[1][pp] = fmaf(w1, ov, acc[1][pp]);
            acc[2][pp] = fmaf(w2, ov, acc[2][pp]);
            acc[3][pp] = fmaf(w3, ov, acc[3][pp]);
        }
    }
    #pragma unroll
    for (int pp = 0; pp < 4; pp++) {
        int lp2 = pbase + pp;
        int gp = (ty0 + (lp2 >> 3)) * 64 + tx0 + (lp2 & 7);
        size_t base = ((size_t)b * NPIX + gp) * CCH;
        #pragma unroll
        for (int cc = 0; cc < 4; cc++) {
            int c = cbase + cc;
            g_t[base + c] = acc[cc][pp] + outb[c] + xn[base + c];
        }
    }
}

__global__ void __launch_bounds__(128) k_ff(const float* __restrict__ xprev,
                                            const float* __restrict__ lw, const float* __restrict__ lb,
                                            const float* __restrict__ w1, const float* __restrict__ b1,
                                            const float* __restrict__ w2, const float* __restrict__ b2,
                                            float* __restrict__ xout) {
    __shared__ float tsh[16 * 64];
    __shared__ float ysh[16 * 64];
    __shared__ float hsh[16 * 64];
    __shared__ float Wsh[64 * 65];
    int tid = threadIdx.x;
    int b = blockIdx.x >> 8;
    int p0 = (blockIdx.x & 255) << 4;
    #pragma unroll
    for (int i = 0; i < 8; i++) {
        int lin = tid + i * 128;
        tsh[lin] = g_t[((size_t)b * NPIX + p0) * CCH + lin];
    }
    __syncthreads();
    int warp = tid >> 5, lane = tid & 31;
    #pragma unroll
    for (int k = 0; k < 4; k++) {
        int pix = warp * 4 + k;
        float v0 = tsh[pix * 64 + lane], v1 = tsh[pix * 64 + lane + 32];
        float s = v0 + v1, sq = v0 * v0 + v1 * v1;
        #pragma unroll
        for (int o = 16; o > 0; o >>= 1) {
            s += __shfl_xor_sync(0xffffffffu, s, o);
            sq += __shfl_xor_sync(0xffffffffu, sq, o);
        }
        float mu = s * (1.f / 64.f);
        float rsg = rsqrtf(sq * (1.f / 64.f) - mu * mu + 1e-5f);
        ysh[pix * 64 + lane] = (v0 - mu) * rsg * lw[lane] + lb[lane];
        ysh[pix * 64 + lane + 32] = (v1 - mu) * rsg * lw[lane + 32] + lb[lane + 32];
    }
    __syncthreads();
    #pragma unroll
    for (int i = 0; i < 32; i++) {
        int lin = tid + i * 128;
        Wsh[(lin & 63) * 65 + (lin >> 6)] = w1[(lin >> 6) * 64 + (lin & 63)];
    }
    __syncthreads();
    int cg = tid & 15, pg = tid >> 4;
    int cbase = cg * 4, pbase = pg * 2;
    {
        float acc[4][2] = {};
        #pragma unroll 4
        for (int k = 0; k < 64; k++) {
            float w0 = Wsh[k * 65 + cbase + 0];
            float w1v = Wsh[k * 65 + cbase + 1];
            float w2v = Wsh[k * 65 + cbase + 2];
            float w3v = Wsh[k * 65 + cbase + 3];
            #pragma unroll
            for (int pp = 0; pp < 2; pp++) {
                float y = ysh[(pbase + pp) * 64 + k];
                acc[0][pp] = fmaf(w0, y, acc[0][pp]);
                acc[1][pp] = fmaf(w1v, y, acc[1][pp]);
                acc[2][pp] = fmaf(w2v, y, acc[2][pp]);
                acc[3][pp] = fmaf(w3v, y, acc[3][pp]);
            }
        }
        #pragma unroll
        for (int pp = 0; pp < 2; pp++)
            #pragma unroll
            for (int cc = 0; cc < 4; cc++) {
                float h = acc[cc][pp] + b1[cbase + cc];
                hsh[(pbase + pp) * 64 + cbase + cc] = 0.5f * h * (1.f + erff(h * 0.70710678118654752f));
            }
    }
    __syncthreads();
    #pragma unroll
    for (int i = 0; i < 32; i++) {
        int lin = tid + i * 128;
        Wsh[(lin & 63) * 65 + (lin >> 6)] = w2[(lin >> 6) * 64 + (lin & 63)];
    }
    __syncthreads();
    {
        float acc[4][2] = {};
        #pragma unroll 4
        for (int k = 0; k < 64; k++) {
            float w0 = Wsh[k * 65 + cbase + 0];
            float w1v = Wsh[k * 65 + cbase + 1];
            float w2v = Wsh[k * 65 + cbase + 2];
            float w3v = Wsh[k * 65 + cbase + 3];
            #pragma unroll
            for (int pp = 0; pp < 2; pp++) {
                float y = hsh[(pbase + pp) * 64 + k];
                acc[0][pp] = fmaf(w0, y, acc[0][pp]);
                acc[1][pp] = fmaf(w1v, y, acc[1][pp]);
                acc[2][pp] = fmaf(w2v, y, acc[2][pp]);
                acc[3][pp] = fmaf(w3v, y, acc[3][pp]);
            }
        }
        #pragma unroll
        for (int pp = 0; pp < 2; pp++) {
            int lpix = pbase + pp;
            size_t base = ((size_t)b * NPIX + p0 + lpix) * CCH;
            #pragma unroll
            for (int cc = 0; cc < 4; cc++) {
                int c = cbase + cc;
                float val = acc[cc][pp] + b2[c] + tsh[lpix * 64 + c];
                if (c == 0) val = xprev[base];
                xout[base + c] = val;
            }
        }
    }
}

extern "C" void kernel_launch(void* const* d_in, const int* in_sizes, int n_in,
                              void* d_out, int out_size) {
    const float* x = (const float*)d_in[0];
    const void* masks = d_in[1];
    const float* p0_w = (const float*)d_in[2];
    const float* p0_b = (const float*)d_in[3];
    const float* p1_w = (const float*)d_in[4];
    const float* p1_b = (const float*)d_in[5];
    const float* fc0_w = (const float*)d_in[6];
    const float* fc0_b = (const float*)d_in[7];
    const float* fc1_w = (const float*)d_in[8];
    const float* n0w = (const float*)d_in[9];
    const float* n0b = (const float*)d_in[10];
    const float* ln1w = (const float*)d_in[11];
    const float* ln1b = (const float*)d_in[12];
    const float* qkvw = (const float*)d_in[13];
    const float* outw = (const float*)d_in[14];
    const float* outb = (const float*)d_in[15];
    const float* ln2w = (const float*)d_in[16];
    const float* ln2b = (const float*)d_in[17];
    const float* ff1w = (const float*)d_in[18];
    const float* ff1b = (const float*)d_in[19];
    const float* ff2w = (const float*)d_in[20];
    const float* ff2b = (const float*)d_in[21];
    float* out = (float*)d_out;

    k_fold<<<288, 256>>>(fc0_w, fc0_b, p0_w, p0_b, p1_w, p1_b);
    k_maskdetect<<<1, 1024>>>((const unsigned char*)masks, 6 * BATCH * NPIX);

    void* sym = nullptr;
    cudaGetSymbolAddress(&sym, g_xbuf);
    float* buf0 = (float*)sym;
    float* buf1 = buf0 + BATCH * NPIX * CCH;

    const float* cur = x;
    for (int s = 0; s < 6; s++) {
        float* stage = (s & 1) ? buf1 : buf0;
        float* nxt = (s == 5) ? out : stage;
        k_conv<<<256, 256>>>(cur);
        k_stats<<<8, 32>>>();
        k_fc1<<<1024, 128>>>(cur, n0w, n0b, fc1_w, masks, s, stage);
        k_qkv<<<1024, 128>>>(stage, ln1w, ln1b, qkvw);
        k_attn<<<1024, 128>>>(stage, outw, outb);
        k_ff<<<2048, 128>>>(cur, ln2w, ln2b, ff1w, ff1b, ff2w, ff2b, nxt);
        cur = nxt;
    }
}

// round 5
// speedup vs baseline: 1.2077x; 1.2077x over previous
#include <cuda_runtime.h>
#include <math.h>
#include <stdint.h>

#define BATCH 8
#define NPIX 4096
#define CCH 64
#define HID 128
#define K3 576
#define ATT_SCALE 0.25f

static __device__ float g_Weff[K3 * HID];
static __device__ float g_Wtf[K3 * HID];       // tf32-rounded copy
static __device__ float g_beff[HID];
static __device__ float g_xbuf[2][BATCH * NPIX * CCH];
static __device__ float g_hd[BATCH * NPIX * HID];
static __device__ float g_part[256 * 2];
static __device__ float g_stats[BATCH * 2];
static __device__ float g_q[BATCH * NPIX * CCH];
static __device__ float g_k[BATCH * NPIX * CCH];
static __device__ float g_v[BATCH * NPIX * CCH];
static __device__ float g_t[BATCH * NPIX * CCH];
static __device__ int g_maskmode;

__device__ __forceinline__ uint32_t f2tf32(float f) {
    uint32_t u;
    asm("cvt.rna.tf32.f32 %0, %1;" : "=r"(u) : "f"(f));
    return u;
}

__global__ void k_maskdetect(const unsigned char* m, int nbytes) {
    __shared__ int hasBig, hasMis;
    if (threadIdx.x == 0) { hasBig = 0; hasMis = 0; }
    __syncthreads();
    for (int i = threadIdx.x; i < nbytes; i += blockDim.x) {
        unsigned char v = m[i];
        if (v > 1) hasBig = 1;
        else if (v && (i & 3)) hasMis = 1;
    }
    __syncthreads();
    if (threadIdx.x == 0) g_maskmode = (!hasBig && hasMis) ? 1 : 0;
}

__global__ void k_fold(const float* __restrict__ fc0_w, const float* __restrict__ fc0_b,
                       const float* __restrict__ p0_w, const float* __restrict__ p0_b,
                       const float* __restrict__ p1_w, const float* __restrict__ p1_b) {
    int t = blockIdx.x * 256 + threadIdx.x;
    if (t >= HID * K3) return;
    int o = t / K3, k = t - o * K3;
    int tap = k >> 6, c = k & 63;
    const float* f1 = fc0_w + o * 192 + 64;
    const float* f2 = fc0_w + o * 192 + 128;
    float acc = 0.f;
    for (int m = 0; m < 64; m++) {
        acc = fmaf(f1[m], p0_w[(m * 64 + c) * 9 + tap], acc);
        acc = fmaf(f2[m], p1_w[(m * 64 + c) * 9 + tap], acc);
    }
    if (tap == 4) acc += fc0_w[o * 192 + c];
    g_Weff[k * HID + o] = acc;
    g_Wtf[k * HID + o] = __uint_as_float(f2tf32(acc));
    if (k == 0) {
        float b = fc0_b[o];
        for (int m = 0; m < 64; m++) {
            b = fmaf(f1[m], p0_b[m], b);
            b = fmaf(f2[m], p1_b[m], b);
        }
        g_beff[o] = b;
    }
}

__device__ __forceinline__ int refl(int v) { return v < 0 ? -v : (v > 63 ? 126 - v : v); }

// ---------------- tensor-core conv: 128 pix x 128 out per block, tf32 MMA ----------------
#define XH_STRIDE 68
#define XH_FLOATS (264 * 68)      // 4 halo rows * 66 cols = 264 positions, 64ch padded to 68
#define W_STRIDE 68
#define W_FLOATS (128 * 68)
#define CONV_SMEM_BYTES ((XH_FLOATS + W_FLOATS) * 4)

__device__ __forceinline__ void mma_tf32(float* c, const uint32_t* a, uint32_t b0, uint32_t b1) {
    asm volatile(
        "mma.sync.aligned.m16n8k8.row.col.f32.tf32.tf32.f32 "
        "{%0,%1,%2,%3}, {%4,%5,%6,%7}, {%8,%9}, {%0,%1,%2,%3};"
        : "+f"(c[0]), "+f"(c[1]), "+f"(c[2]), "+f"(c[3])
        : "r"(a[0]), "r"(a[1]), "r"(a[2]), "r"(a[3]), "r"(b0), "r"(b1));
}

__global__ void __launch_bounds__(256) k_conv_mma(const float* __restrict__ xin) {
    extern __shared__ float sm[];
    float* Xh = sm;                 // [264][68]
    float* Wsh = sm + XH_FLOATS;    // [128][68]  (out-major, k minor)
    int tid = threadIdx.x;
    int batch = blockIdx.x >> 5;
    int y0 = (blockIdx.x & 31) << 1;
    const float* xb = xin + (size_t)batch * NPIX * CCH;

    // stage 4x66 halo (reflect), tf32-rounded
    #pragma unroll 2
    for (int i = 0; i < 66; i++) {
        int lin = i * 256 + tid;
        int ch = lin & 63;
        int hp = lin >> 6;          // 0..263
        int hr = hp / 66, hc = hp - hr * 66;
        int gy = refl(y0 + hr - 1), gx = refl(hc - 1);
        float v = xb[(gy * 64 + gx) * CCH + ch];
        Xh[hp * XH_STRIDE + ch] = __uint_as_float(f2tf32(v));
    }

    int warp = tid >> 5, lane = tid & 31;
    int g = lane >> 2, t4 = lane & 3;
    int pixBase = (warp >> 1) * 32;       // 4 warps in M
    int nBase = (warp & 1) * 64;          // 2 warps in N

    float acc[2][8][4];
    #pragma unroll
    for (int m = 0; m < 2; m++)
        #pragma unroll
        for (int n = 0; n < 8; n++)
            #pragma unroll
            for (int j = 0; j < 4; j++) acc[m][n][j] = 0.f;

    for (int tap = 0; tap < 9; tap++) {
        int dy = tap / 3, dx = tap - dy * 3;      // halo offsets (0..2)
        __syncthreads();
        // stage weights for this tap: [64 k][128 out] -> Wsh[out][k]
        #pragma unroll
        for (int i = 0; i < 32; i++) {
            int lin = i * 256 + tid;
            int o = lin & 127, k = lin >> 7;
            Wsh[o * W_STRIDE + k] = g_Wtf[(tap * 64 + k) * HID + o];
        }
        __syncthreads();

        // precompute halo row bases for this warp's two m-frags
        #pragma unroll
        for (int k0 = 0; k0 < 64; k0 += 8) {
            uint32_t a[2][4];
            #pragma unroll
            for (int m = 0; m < 2; m++) {
                int p = pixBase + m * 16 + g;
                int hb = ((p >> 6) + dy) * 66 + (p & 63) + dx;
                const float* ap = &Xh[hb * XH_STRIDE + k0 + t4];
                a[m][0] = __float_as_uint(ap[0]);
                a[m][2] = __float_as_uint(ap[4]);
                int p8 = p + 8;
                int hb8 = ((p8 >> 6) + dy) * 66 + (p8 & 63) + dx;
                const float* ap8 = &Xh[hb8 * XH_STRIDE + k0 + t4];
                a[m][1] = __float_as_uint(ap8[0]);
                a[m][3] = __float_as_uint(ap8[4]);
            }
            #pragma unroll
            for (int n = 0; n < 8; n++) {
                const float* bp = &Wsh[(nBase + n * 8 + g) * W_STRIDE + k0 + t4];
                uint32_t b0 = __float_as_uint(bp[0]);
                uint32_t b1 = __float_as_uint(bp[4]);
                mma_tf32(acc[0][n], a[0], b0, b1);
                mma_tf32(acc[1][n], a[1], b0, b1);
            }
        }
    }
    __syncthreads();

    // epilogue: bias + relu + store + LN partial sums
    float s = 0.f, sq = 0.f;
    #pragma unroll
    for (int m = 0; m < 2; m++) {
        int p_lo = pixBase + m * 16 + g;
        int p_hi = p_lo + 8;
        size_t row_lo = ((size_t)batch * NPIX + y0 * 64 + p_lo) * HID;
        size_t row_hi = ((size_t)batch * NPIX + y0 * 64 + p_hi) * HID;
        #pragma unroll
        for (int n = 0; n < 8; n++) {
            int col = nBase + n * 8 + 2 * t4;
            float bo0 = g_beff[col], bo1 = g_beff[col + 1];
            float r0 = fmaxf(acc[m][n][0] + bo0, 0.f);
            float r1 = fmaxf(acc[m][n][1] + bo1, 0.f);
            float r2 = fmaxf(acc[m][n][2] + bo0, 0.f);
            float r3 = fmaxf(acc[m][n][3] + bo1, 0.f);
            *(float2*)&g_hd[row_lo + col] = make_float2(r0, r1);
            *(float2*)&g_hd[row_hi + col] = make_float2(r2, r3);
            s += r0 + r1 + r2 + r3;
            sq += r0 * r0 + r1 * r1 + r2 * r2 + r3 * r3;
        }
    }
    float* red = sm;   // reuse smem
    red[tid] = s; red[256 + tid] = sq;
    __syncthreads();
    for (int st = 128; st > 0; st >>= 1) {
        if (tid < st) { red[tid] += red[tid + st]; red[256 + tid] += red[256 + tid + st]; }
        __syncthreads();
    }
    if (tid == 0) { g_part[blockIdx.x * 2] = red[0]; g_part[blockIdx.x * 2 + 1] = red[256]; }
}

__global__ void k_stats() {
    int b = blockIdx.x, lane = threadIdx.x;
    float s = g_part[(b * 32 + lane) * 2];
    float sq = g_part[(b * 32 + lane) * 2 + 1];
    #pragma unroll
    for (int o = 16; o > 0; o >>= 1) {
        s += __shfl_xor_sync(0xffffffffu, s, o);
        sq += __shfl_xor_sync(0xffffffffu, sq, o);
    }
    if (lane == 0) {
        const float inv = 1.f / 524288.f;
        float mu = s * inv;
        g_stats[b * 2] = mu;
        g_stats[b * 2 + 1] = rsqrtf(sq * inv - mu * mu + 1e-5f);
    }
}

__global__ void __launch_bounds__(128) k_fc1(const float* __restrict__ xin,
                                             const float* __restrict__ nw, const float* __restrict__ nb,
                                             const float* __restrict__ fc1_w,
                                             const void* __restrict__ mask, int s,
                                             float* __restrict__ xout) {
    __shared__ float ysh[32 * 128];
    __shared__ float Wsh[64 * 65];
    int tid = threadIdx.x;
    int b = blockIdx.x >> 7;
    int p0 = (blockIdx.x & 127) << 5;
    float mu = g_stats[b * 2], rs = g_stats[b * 2 + 1];
    #pragma unroll
    for (int i = 0; i < 32; i++) {
        int lin = tid + i * 128;
        size_t gi = ((size_t)b * NPIX + p0) * HID + lin;
        int ii = p0 * HID + lin;
        ysh[lin] = (g_hd[gi] - mu) * rs * nw[ii] + nb[ii];
    }
    int cg = tid & 15, pg = tid >> 4;
    int cbase = cg * 4, pbase = pg * 4;
    float acc[4][4] = {};
    for (int hc = 0; hc < 128; hc += 64) {
        __syncthreads();
        #pragma unroll
        for (int i = 0; i < 32; i++) {
            int lin = tid + i * 128;
            Wsh[(lin & 63) * 65 + (lin >> 6)] = fc1_w[(lin >> 6) * 128 + hc + (lin & 63)];
        }
        __syncthreads();
        #pragma unroll 4
        for (int h = 0; h < 64; h++) {
            float w0 = Wsh[h * 65 + cbase + 0];
            float w1 = Wsh[h * 65 + cbase + 1];
            float w2 = Wsh[h * 65 + cbase + 2];
            float w3 = Wsh[h * 65 + cbase + 3];
            #pragma unroll
            for (int pp = 0; pp < 4; pp++) {
                float y = ysh[(pbase + pp) * 128 + hc + h];
                acc[0][pp] = fmaf(w0, y, acc[0][pp]);
                acc[1][pp] = fmaf(w1, y, acc[1][pp]);
                acc[2][pp] = fmaf(w2, y, acc[2][pp]);
                acc[3][pp] = fmaf(w3, y, acc[3][pp]);
            }
        }
    }
    int mode = g_maskmode;
    #pragma unroll
    for (int pp = 0; pp < 4; pp++) {
        size_t gp = (size_t)b * NPIX + p0 + pbase + pp;
        size_t mi = (size_t)s * 32768 + gp;
        float mv;
        if (mode) mv = ((const unsigned char*)mask)[mi] ? 1.f : 0.f;
        else mv = ((const unsigned int*)mask)[mi] ? 1.f : 0.f;
        #pragma unroll
        for (int cc = 0; cc < 4; cc++) {
            int c = cbase + cc;
            xout[gp * CCH + c] = xin[gp * CCH + c] + acc[cc][pp] * mv;
        }
    }
}

__global__ void __launch_bounds__(128) k_qkv(const float* __restrict__ xin,
                                             const float* __restrict__ lw, const float* __restrict__ lb,
                                             const float* __restrict__ qkvw) {
    __shared__ float ysh[32 * 64];
    __shared__ float Wsh[64 * 65];
    int tid = threadIdx.x;
    int b = blockIdx.x >> 7;
    int p0 = (blockIdx.x & 127) << 5;
    int warp = tid >> 5, lane = tid & 31;
    #pragma unroll
    for (int k = 0; k < 8; k++) {
        int pix = warp * 8 + k;
        size_t base = ((size_t)b * NPIX + p0 + pix) * CCH;
        float v0 = xin[base + lane], v1 = xin[base + lane + 32];
        float s = v0 + v1, sq = v0 * v0 + v1 * v1;
        #pragma unroll
        for (int o = 16; o > 0; o >>= 1) {
            s += __shfl_xor_sync(0xffffffffu, s, o);
            sq += __shfl_xor_sync(0xffffffffu, sq, o);
        }
        float mu = s * (1.f / 64.f);
        float rsg = rsqrtf(sq * (1.f / 64.f) - mu * mu + 1e-5f);
        ysh[pix * 64 + lane] = (v0 - mu) * rsg * lw[lane] + lb[lane];
        ysh[pix * 64 + lane + 32] = (v1 - mu) * rsg * lw[lane + 32] + lb[lane + 32];
    }
    int cg = tid & 15, pg = tid >> 4;
    int obase = cg * 4, pbase = pg * 4;
    float* outs[3] = {g_q, g_k, g_v};
    for (int ch = 0; ch < 3; ch++) {
        __syncthreads();
        #pragma unroll
        for (int i = 0; i < 32; i++) {
            int lin = tid + i * 128;
            Wsh[(lin & 63) * 65 + (lin >> 6)] = qkvw[(ch * 64 + (lin >> 6)) * 64 + (lin & 63)];
        }
        __syncthreads();
        float acc[4][4] = {};
        #pragma unroll 4
        for (int k = 0; k < 64; k++) {
            float w0 = Wsh[k * 65 + obase + 0];
            float w1 = Wsh[k * 65 + obase + 1];
            float w2 = Wsh[k * 65 + obase + 2];
            float w3 = Wsh[k * 65 + obase + 3];
            #pragma unroll
            for (int pp = 0; pp < 4; pp++) {
                float y = ysh[(pbase + pp) * 64 + k];
                acc[0][pp] = fmaf(w0, y, acc[0][pp]);
                acc[1][pp] = fmaf(w1, y, acc[1][pp]);
                acc[2][pp] = fmaf(w2, y, acc[2][pp]);
                acc[3][pp] = fmaf(w3, y, acc[3][pp]);
            }
        }
        float* op = outs[ch];
        #pragma unroll
        for (int pp = 0; pp < 4; pp++) {
            size_t base = ((size_t)b * NPIX + p0 + pbase + pp) * CCH;
            #pragma unroll
            for (int cc = 0; cc < 4; cc++) op[base + obase + cc] = acc[cc][pp];
        }
    }
}

__global__ void __launch_bounds__(128) k_attn(const float* __restrict__ xn,
                                              const float* __restrict__ outw,
                                              const float* __restrict__ outb) {
    __shared__ float sm2[64 * 61 * 2 + 32 * 65];
    float* ksh = sm2;
    float* vsh = sm2 + 64 * 61;
    float* osh = sm2 + 64 * 61 * 2;
    int tid = threadIdx.x;
    int b = blockIdx.x >> 7;
    int tile = blockIdx.x & 127;
    int tx0 = (tile & 7) << 3;
    int ty0 = (tile >> 3) << 2;
    #pragma unroll
    for (int i = 0; i < 30; i++) {
        int lin = tid + i * 128;
        int pos = lin >> 6, ch = lin & 63;
        int hy = pos / 10, hx = pos - hy * 10;
        int gy = ty0 + hy - 1, gx = tx0 + hx - 1;
        float kv = 0.f, vv = 0.f;
        if ((unsigned)gy < 64u && (unsigned)gx < 64u) {
            size_t a = ((size_t)b * NPIX + gy * 64 + gx) * CCH + ch;
            kv = g_k[a]; vv = g_v[a];
        }
        ksh[ch * 61 + pos] = kv;
        vsh[ch * 61 + pos] = vv;
    }
    __syncthreads();
    {
        int head = tid >> 5, lp = tid & 31;
        int py = lp >> 3, px = lp & 7;
        int gy = ty0 + py, gx = tx0 + px;
        size_t qbase = ((size_t)b * NPIX + gy * 64 + gx) * CCH + head * 16;
        float q[16];
        #pragma unroll
        for (int i = 0; i < 4; i++) {
            float4 t4 = *(const float4*)&g_q[qbase + i * 4];
            q[i * 4] = t4.x; q[i * 4 + 1] = t4.y; q[i * 4 + 2] = t4.z; q[i * 4 + 3] = t4.w;
        }
        float lg[9];
        #pragma unroll
        for (int t = 0; t < 9; t++) {
            int pos = (py + t / 3) * 10 + px + t % 3;
            float d = 0.f;
            #pragma unroll
            for (int i = 0; i < 16; i++) d = fmaf(q[i], ksh[(head * 16 + i) * 61 + pos], d);
            lg[t] = d * ATT_SCALE;
        }
        float m = lg[0];
        #pragma unroll
        for (int t = 1; t < 9; t++) m = fmaxf(m, lg[t]);
        float e[9], ssum = 0.f;
        #pragma unroll
        for (int t = 0; t < 9; t++) { e[t] = __expf(lg[t] - m); ssum += e[t]; }
        float inv = 1.f / ssum;
        float o[16] = {};
        #pragma unroll
        for (int t = 0; t < 9; t++) {
            int pos = (py + t / 3) * 10 + px + t % 3;
            float a = e[t] * inv;
            #pragma unroll
            for (int i = 0; i < 16; i++) o[i] = fmaf(a, vsh[(head * 16 + i) * 61 + pos], o[i]);
        }
        #pragma unroll
        for (int i = 0; i < 16; i++) osh[lp * 65 + head * 16 + i] = o[i];
    }
    __syncthreads();
    float* wsh = sm2;
    #pragma unroll
    for (int i = 0; i < 32; i++) {
        int lin = tid + i * 128;
        wsh[(lin & 63) * 65 + (lin >> 6)] = outw[(lin >> 6) * 64 + (lin & 63)];
    }
    __syncthreads();
    int cg = tid & 15, pg = tid >> 4;
    int cbase = cg * 4, pbase = pg * 4;
    float acc[4][4] = {};
    #pragma unroll 4
    for (int k = 0; k < 64; k++) {
        float w0 = wsh[k * 65 + cbase + 0];
        float w1 = wsh[k * 65 + cbase + 1];
        float w2 = wsh[k * 65 + cbase + 2];
        float w3 = wsh[k * 65 + cbase + 3];
        #pragma unroll
        for (int pp = 0; pp < 4; pp++) {
            float ov = osh[(pbase + pp) * 65 + k];
            acc[0][pp] = fmaf(w0, ov, acc[0][pp]);
            acc[1][pp] = fmaf(w1, ov, acc[1][pp]);
            acc[2][pp] = fmaf(w2, ov, acc[2][pp]);
            acc[3][pp] = fmaf(w3, ov, acc[3][pp]);
        }
    }
    #pragma unroll
    for (int pp = 0; pp < 4; pp++) {
        int lp2 = pbase + pp;
        int gp = (ty0 + (lp2 >> 3)) * 64 + tx0 + (lp2 & 7);
        size_t base = ((size_t)b * NPIX + gp) * CCH;
        #pragma unroll
        for (int cc = 0; cc < 4; cc++) {
            int c = cbase + cc;
            g_t[base + c] = acc[cc][pp] + outb[c] + xn[base + c];
        }
    }
}

__global__ void __launch_bounds__(128) k_ff(const float* __restrict__ xprev,
                                            const float* __restrict__ lw, const float* __restrict__ lb,
                                            const float* __restrict__ w1, const float* __restrict__ b1,
                                            const float* __restrict__ w2, const float* __restrict__ b2,
                                            float* __restrict__ xout) {
    __shared__ float tsh[16 * 64];
    __shared__ float ysh[16 * 64];
    __shared__ float hsh[16 * 64];
    __shared__ float Wsh[64 * 65];
    int tid = threadIdx.x;
    int b = blockIdx.x >> 8;
    int p0 = (blockIdx.x & 255) << 4;
    #pragma unroll
    for (int i = 0; i < 8; i++) {
        int lin = tid + i * 128;
        tsh[lin] = g_t[((size_t)b * NPIX + p0) * CCH + lin];
    }
    __syncthreads();
    int warp = tid >> 5, lane = tid & 31;
    #pragma unroll
    for (int k = 0; k < 4; k++) {
        int pix = warp * 4 + k;
        float v0 = tsh[pix * 64 + lane], v1 = tsh[pix * 64 + lane + 32];
        float s = v0 + v1, sq = v0 * v0 + v1 * v1;
        #pragma unroll
        for (int o = 16; o > 0; o >>= 1) {
            s += __shfl_xor_sync(0xffffffffu, s, o);
            sq += __shfl_xor_sync(0xffffffffu, sq, o);
        }
        float mu = s * (1.f / 64.f);
        float rsg = rsqrtf(sq * (1.f / 64.f) - mu * mu + 1e-5f);
        ysh[pix * 64 + lane] = (v0 - mu) * rsg * lw[lane] + lb[lane];
        ysh[pix * 64 + lane + 32] = (v1 - mu) * rsg * lw[lane + 32] + lb[lane + 32];
    }
    __syncthreads();
    #pragma unroll
    for (int i = 0; i < 32; i++) {
        int lin = tid + i * 128;
        Wsh[(lin & 63) * 65 + (lin >> 6)] = w1[(lin >> 6) * 64 + (lin & 63)];
    }
    __syncthreads();
    int cg = tid & 15, pg = tid >> 4;
    int cbase = cg * 4, pbase = pg * 2;
    {
        float acc[4][2] = {};
        #pragma unroll 4
        for (int k = 0; k < 64; k++) {
            float w0 = Wsh[k * 65 + cbase + 0];
            float w1v = Wsh[k * 65 + cbase + 1];
            float w2v = Wsh[k * 65 + cbase + 2];
            float w3v = Wsh[k * 65 + cbase + 3];
            #pragma unroll
            for (int pp = 0; pp < 2; pp++) {
                float y = ysh[(pbase + pp) * 64 + k];
                acc[0][pp] = fmaf(w0, y, acc[0][pp]);
                acc[1][pp] = fmaf(w1v, y, acc[1][pp]);
                acc[2][pp] = fmaf(w2v, y, acc[2][pp]);
                acc[3][pp] = fmaf(w3v, y, acc[3][pp]);
            }
        }
        #pragma unroll
        for (int pp = 0; pp < 2; pp++)
            #pragma unroll
            for (int cc = 0; cc < 4; cc++) {
                float h = acc[cc][pp] + b1[cbase + cc];
                hsh[(pbase + pp) * 64 + cbase + cc] = 0.5f * h * (1.f + erff(h * 0.70710678118654752f));
            }
    }
    __syncthreads();
    #pragma unroll
    for (int i = 0; i < 32; i++) {
        int lin = tid + i * 128;
        Wsh[(lin & 63) * 65 + (lin >> 6)] = w2[(lin >> 6) * 64 + (lin & 63)];
    }
    __syncthreads();
    {
        float acc[4][2] = {};
        #pragma unroll 4
        for (int k = 0; k < 64; k++) {
            float w0 = Wsh[k * 65 + cbase + 0];
            float w1v = Wsh[k * 65 + cbase + 1];
            float w2v = Wsh[k * 65 + cbase + 2];
            float w3v = Wsh[k * 65 + cbase + 3];
            #pragma unroll
            for (int pp = 0; pp < 2; pp++) {
                float y = hsh[(pbase + pp) * 64 + k];
                acc[0][pp] = fmaf(w0, y, acc[0][pp]);
                acc[1][pp] = fmaf(w1v, y, acc[1][pp]);
                acc[2][pp] = fmaf(w2v, y, acc[2][pp]);
                acc[3][pp] = fmaf(w3v, y, acc[3][pp]);
            }
        }
        #pragma unroll
        for (int pp = 0; pp < 2; pp++) {
            int lpix = pbase + pp;
            size_t base = ((size_t)b * NPIX + p0 + lpix) * CCH;
            #pragma unroll
            for (int cc = 0; cc < 4; cc++) {
                int c = cbase + cc;
                float val = acc[cc][pp] + b2[c] + tsh[lpix * 64 + c];
                if (c == 0) val = xprev[base];
                xout[base + c] = val;
            }
        }
    }
}

extern "C" void kernel_launch(void* const* d_in, const int* in_sizes, int n_in,
                              void* d_out, int out_size) {
    const float* x = (const float*)d_in[0];
    const void* masks = d_in[1];
    const float* p0_w = (const float*)d_in[2];
    const float* p0_b = (const float*)d_in[3];
    const float* p1_w = (const float*)d_in[4];
    const float* p1_b = (const float*)d_in[5];
    const float* fc0_w = (const float*)d_in[6];
    const float* fc0_b = (const float*)d_in[7];
    const float* fc1_w = (const float*)d_in[8];
    const float* n0w = (const float*)d_in[9];
    const float* n0b = (const float*)d_in[10];
    const float* ln1w = (const float*)d_in[11];
    const float* ln1b = (const float*)d_in[12];
    const float* qkvw = (const float*)d_in[13];
    const float* outw = (const float*)d_in[14];
    const float* outb = (const float*)d_in[15];
    const float* ln2w = (const float*)d_in[16];
    const float* ln2b = (const float*)d_in[17];
    const float* ff1w = (const float*)d_in[18];
    const float* ff1b = (const float*)d_in[19];
    const float* ff2w = (const float*)d_in[20];
    const float* ff2b = (const float*)d_in[21];
    float* out = (float*)d_out;

    static int s_attr_done = 0;
    if (!s_attr_done) {
        cudaFuncSetAttribute(k_conv_mma, cudaFuncAttributeMaxDynamicSharedMemorySize,
                             CONV_SMEM_BYTES);
        s_attr_done = 1;
    }

    k_fold<<<288, 256>>>(fc0_w, fc0_b, p0_w, p0_b, p1_w, p1_b);
    k_maskdetect<<<1, 1024>>>((const unsigned char*)masks, 6 * BATCH * NPIX);

    void* sym = nullptr;
    cudaGetSymbolAddress(&sym, g_xbuf);
    float* buf0 = (float*)sym;
    float* buf1 = buf0 + BATCH * NPIX * CCH;

    const float* cur = x;
    for (int s = 0; s < 6; s++) {
        float* stage = (s & 1) ? buf1 : buf0;
        float* nxt = (s == 5) ? out : stage;
        k_conv_mma<<<256, 256, CONV_SMEM_BYTES>>>(cur);
        k_stats<<<8, 32>>>();
        k_fc1<<<1024, 128>>>(cur, n0w, n0b, fc1_w, masks, s, stage);
        k_qkv<<<1024, 128>>>(stage, ln1w, ln1b, qkvw);
        k_attn<<<1024, 128>>>(stage, outw, outb);
        k_ff<<<2048, 128>>>(cur, ln2w, ln2b, ff1w, ff1b, ff2w, ff2b, nxt);
        cur = nxt;
    }
}

// round 7
// speedup vs baseline: 1.2924x; 1.0701x over previous
#include <cuda_runtime.h>
#include <math.h>
#include <stdint.h>

#define BATCH 8
#define NPIX 4096
#define CCH 64
#define HID 128
#define K3 576
#define ATT_SCALE 0.25f

static __device__ float g_Wswz[9 * 128 * 64];   // pre-swizzled tf32 conv weights [tap][o][64]
static __device__ float g_beff[HID];
static __device__ float g_xbuf[2][BATCH * NPIX * CCH];
static __device__ float g_hd[BATCH * NPIX * HID];
static __device__ float g_part[256 * 2];
static __device__ float g_stats[BATCH * 2];
static __device__ float g_q[BATCH * NPIX * CCH];
static __device__ float g_k[BATCH * NPIX * CCH];
static __device__ float g_v[BATCH * NPIX * CCH];
static __device__ float g_t[BATCH * NPIX * CCH];
static __device__ int g_maskmode;

__device__ __forceinline__ uint32_t f2tf32(float f) {
    uint32_t u;
    asm("cvt.rna.tf32.f32 %0, %1;" : "=r"(u) : "f"(f));
    return u;
}

// swizzled chunk index for channel/k index c within a 64-float row of parity (row&1)
__device__ __forceinline__ int swz_pos(int c, int rowpar) {
    int t4 = c & 3, idx = c >> 2;
    int pi = (t4 * 4 + (((idx >> 2) + t4) & 3)) ^ rowpar;
    return pi * 4 + (idx & 3);
}

__global__ void k_maskdetect(const unsigned char* m, int nbytes) {
    __shared__ int hasBig, hasMis;
    if (threadIdx.x == 0) { hasBig = 0; hasMis = 0; }
    __syncthreads();
    for (int i = threadIdx.x; i < nbytes; i += blockDim.x) {
        unsigned char v = m[i];
        if (v > 1) hasBig = 1;
        else if (v && (i & 3)) hasMis = 1;
    }
    __syncthreads();
    if (threadIdx.x == 0) g_maskmode = (!hasBig && hasMis) ? 1 : 0;
}

__global__ void k_fold(const float* __restrict__ fc0_w, const float* __restrict__ fc0_b,
                       const float* __restrict__ p0_w, const float* __restrict__ p0_b,
                       const float* __restrict__ p1_w, const float* __restrict__ p1_b) {
    int t = blockIdx.x * 256 + threadIdx.x;
    if (t >= HID * K3) return;
    int o = t / K3, k = t - o * K3;
    int tap = k >> 6, c = k & 63;
    const float* f1 = fc0_w + o * 192 + 64;
    const float* f2 = fc0_w + o * 192 + 128;
    float acc = 0.f;
    for (int m = 0; m < 64; m++) {
        acc = fmaf(f1[m], p0_w[(m * 64 + c) * 9 + tap], acc);
        acc = fmaf(f2[m], p1_w[(m * 64 + c) * 9 + tap], acc);
    }
    if (tap == 4) acc += fc0_w[o * 192 + c];
    g_Wswz[(tap * 128 + o) * 64 + swz_pos(c, o & 1)] = __uint_as_float(f2tf32(acc));
    if (k == 0) {
        float b = fc0_b[o];
        for (int m = 0; m < 64; m++) {
            b = fmaf(f1[m], p0_b[m], b);
            b = fmaf(f2[m], p1_b[m], b);
        }
        g_beff[o] = b;
    }
}

__device__ __forceinline__ int refl(int v) { return v < 0 ? -v : (v > 63 ? 126 - v : v); }

// ---------------- tensor-core conv: 128 pix x 128 out per block, swizzled float4 operands --------
#define XH_FLOATS (264 * 64)
#define W_FLOATS (128 * 64)
#define CONV_SMEM_BYTES ((XH_FLOATS + W_FLOATS) * 4)

__device__ __forceinline__ void mma_tf32(float* c, const uint32_t* a, uint32_t b0, uint32_t b1) {
    asm volatile(
        "mma.sync.aligned.m16n8k8.row.col.f32.tf32.tf32.f32 "
        "{%0,%1,%2,%3}, {%4,%5,%6,%7}, {%8,%9}, {%0,%1,%2,%3};"
        : "+f"(c[0]), "+f"(c[1]), "+f"(c[2]), "+f"(c[3])
        : "r"(a[0]), "r"(a[1]), "r"(a[2]), "r"(a[3]), "r"(b0), "r"(b1));
}

__global__ void __launch_bounds__(256, 2) k_conv_mma(const float* __restrict__ xin) {
    extern __shared__ float sm[];
    float* Xh = sm;                 // [264][64] swizzled
    float* Wsh = sm + XH_FLOATS;    // [128][64] swizzled
    int tid = threadIdx.x;
    int batch = blockIdx.x >> 5;
    int y0 = (blockIdx.x & 31) << 1;
    const float* xb = xin + (size_t)batch * NPIX * CCH;

    // stage 4x66 reflect halo into swizzled layout (conflict-free STS)
    #pragma unroll 2
    for (int i = 0; i < 66; i++) {
        int lin = i * 256 + tid;
        int ch = lin & 63;
        int hp = lin >> 6;          // 0..263
        int hr = hp / 66, hc = hp - hr * 66;
        int gy = refl(y0 + hr - 1), gx = refl(hc - 1);
        float v = xb[(gy * 64 + gx) * CCH + ch];
        Xh[hp * 64 + swz_pos(ch, hp & 1)] = __uint_as_float(f2tf32(v));
    }

    int warp = tid >> 5, lane = tid & 31;
    int g = lane >> 2, t4 = lane & 3;
    int pixBase = (warp >> 1) * 32;       // 4 warps in M
    int nBase = (warp & 1) * 64;          // 2 warps in N

    float acc[2][8][4];
    #pragma unroll
    for (int m = 0; m < 2; m++)
        #pragma unroll
        for (int n = 0; n < 8; n++)
            #pragma unroll
            for (int j2 = 0; j2 < 4; j2++) acc[m][n][j2] = 0.f;

    for (int tap = 0; tap < 9; tap++) {
        int dy = tap / 3, dx = tap - dy * 3;
        __syncthreads();
        // stage this tap's pre-swizzled weights: straight float4 copy
        {
            const float4* wsrc = (const float4*)(g_Wswz + tap * (128 * 64));
            float4* wdst = (float4*)Wsh;
            #pragma unroll
            for (int i = 0; i < 8; i++) wdst[i * 256 + tid] = wsrc[i * 256 + tid];
        }
        __syncthreads();

        #pragma unroll
        for (int j = 0; j < 4; j++) {
            int pibase = t4 * 4 + ((j + t4) & 3);
            // A fragments: 4 rows (p, p+8, p+16, p+24), one float4 each = 16 k-values
            float4 av[4];
            #pragma unroll
            for (int r = 0; r < 4; r++) {
                int pr = pixBase + r * 8 + g;
                int hb = ((pr >> 6) + dy) * 66 + (pr & 63) + dx;
                av[r] = *(const float4*)&Xh[hb * 64 + ((pibase ^ (hb & 1)) << 2)];
            }
            // half0 (kidx=2j): elements .x/.y ; half1 (kidx=2j+1): .z/.w
            uint32_t aH0m0[4] = {__float_as_uint(av[0].x), __float_as_uint(av[1].x),
                                 __float_as_uint(av[0].y), __float_as_uint(av[1].y)};
            uint32_t aH1m0[4] = {__float_as_uint(av[0].z), __float_as_uint(av[1].z),
                                 __float_as_uint(av[0].w), __float_as_uint(av[1].w)};
            uint32_t aH0m1[4] = {__float_as_uint(av[2].x), __float_as_uint(av[3].x),
                                 __float_as_uint(av[2].y), __float_as_uint(av[3].y)};
            uint32_t aH1m1[4] = {__float_as_uint(av[2].z), __float_as_uint(av[3].z),
                                 __float_as_uint(av[2].w), __float_as_uint(av[3].w)};
            #pragma unroll
            for (int n = 0; n < 8; n++) {
                int o = nBase + n * 8 + g;
                float4 bv = *(const float4*)&Wsh[o * 64 + ((pibase ^ (o & 1)) << 2)];
                uint32_t b0 = __float_as_uint(bv.x), b1 = __float_as_uint(bv.y);
                uint32_t b2 = __float_as_uint(bv.z), b3 = __float_as_uint(bv.w);
                mma_tf32(acc[0][n], aH0m0, b0, b1);
                mma_tf32(acc[0][n], aH1m0, b2, b3);
                mma_tf32(acc[1][n], aH0m1, b0, b1);
                mma_tf32(acc[1][n], aH1m1, b2, b3);
            }
        }
    }
    __syncthreads();

    // epilogue: bias + relu + store + LN partial sums
    float s = 0.f, sq = 0.f;
    #pragma unroll
    for (int m = 0; m < 2; m++) {
        int p_lo = pixBase + m * 16 + g;
        int p_hi = p_lo + 8;
        size_t row_lo = ((size_t)batch * NPIX + y0 * 64 + p_lo) * HID;
        size_t row_hi = ((size_t)batch * NPIX + y0 * 64 + p_hi) * HID;
        #pragma unroll
        for (int n = 0; n < 8; n++) {
            int col = nBase + n * 8 + 2 * t4;
            float bo0 = g_beff[col], bo1 = g_beff[col + 1];
            float r0 = fmaxf(acc[m][n][0] + bo0, 0.f);
            float r1 = fmaxf(acc[m][n][1] + bo1, 0.f);
            float r2 = fmaxf(acc[m][n][2] + bo0, 0.f);
            float r3 = fmaxf(acc[m][n][3] + bo1, 0.f);
            *(float2*)&g_hd[row_lo + col] = make_float2(r0, r1);
            *(float2*)&g_hd[row_hi + col] = make_float2(r2, r3);
            s += r0 + r1 + r2 + r3;
            sq += r0 * r0 + r1 * r1 + r2 * r2 + r3 * r3;
        }
    }
    float* red = sm;   // reuse smem
    red[tid] = s; red[256 + tid] = sq;
    __syncthreads();
    for (int st = 128; st > 0; st >>= 1) {
        if (tid < st) { red[tid] += red[tid + st]; red[256 + tid] += red[256 + tid + st]; }
        __syncthreads();
    }
    if (tid == 0) { g_part[blockIdx.x * 2] = red[0]; g_part[blockIdx.x * 2 + 1] = red[256]; }
}

__global__ void k_stats() {
    int b = blockIdx.x, lane = threadIdx.x;
    float s = g_part[(b * 32 + lane) * 2];
    float sq = g_part[(b * 32 + lane) * 2 + 1];
    #pragma unroll
    for (int o = 16; o > 0; o >>= 1) {
        s += __shfl_xor_sync(0xffffffffu, s, o);
        sq += __shfl_xor_sync(0xffffffffu, sq, o);
    }
    if (lane == 0) {
        const float inv = 1.f / 524288.f;
        float mu = s * inv;
        g_stats[b * 2] = mu;
        g_stats[b * 2 + 1] = rsqrtf(sq * inv - mu * mu + 1e-5f);
    }
}

__global__ void __launch_bounds__(128) k_fc1(const float* __restrict__ xin,
                                             const float* __restrict__ nw, const float* __restrict__ nb,
                                             const float* __restrict__ fc1_w,
                                             const void* __restrict__ mask, int s,
                                             float* __restrict__ xout) {
    __shared__ float ysh[32 * 128];
    __shared__ float Wsh[64 * 65];
    int tid = threadIdx.x;
    int b = blockIdx.x >> 7;
    int p0 = (blockIdx.x & 127) << 5;
    float mu = g_stats[b * 2], rs = g_stats[b * 2 + 1];
    #pragma unroll
    for (int i = 0; i < 32; i++) {
        int lin = tid + i * 128;
        size_t gi = ((size_t)b * NPIX + p0) * HID + lin;
        int ii = p0 * HID + lin;
        ysh[lin] = (g_hd[gi] - mu) * rs * nw[ii] + nb[ii];
    }
    int cg = tid & 15, pg = tid >> 4;
    int cbase = cg * 4, pbase = pg * 4;
    float acc[4][4] = {};
    for (int hc = 0; hc < 128; hc += 64) {
        __syncthreads();
        #pragma unroll
        for (int i = 0; i < 32; i++) {
            int lin = tid + i * 128;
            Wsh[(lin & 63) * 65 + (lin >> 6)] = fc1_w[(lin >> 6) * 128 + hc + (lin & 63)];
        }
        __syncthreads();
        #pragma unroll 4
        for (int h = 0; h < 64; h++) {
            float w0 = Wsh[h * 65 + cbase + 0];
            float w1 = Wsh[h * 65 + cbase + 1];
            float w2 = Wsh[h * 65 + cbase + 2];
            float w3 = Wsh[h * 65 + cbase + 3];
            #pragma unroll
            for (int pp = 0; pp < 4; pp++) {
                float y = ysh[(pbase + pp) * 128 + hc + h];
                acc[0][pp] = fmaf(w0, y, acc[0][pp]);
                acc[1][pp] = fmaf(w1, y, acc[1][pp]);
                acc[2][pp] = fmaf(w2, y, acc[2][pp]);
                acc[3][pp] = fmaf(w3, y, acc[3][pp]);
            }
        }
    }
    int mode = g_maskmode;
    #pragma unroll
    for (int pp = 0; pp < 4; pp++) {
        size_t gp = (size_t)b * NPIX + p0 + pbase + pp;
        size_t mi = (size_t)s * 32768 + gp;
        float mv;
        if (mode) mv = ((const unsigned char*)mask)[mi] ? 1.f : 0.f;
        else mv = ((const unsigned int*)mask)[mi] ? 1.f : 0.f;
        #pragma unroll
        for (int cc = 0; cc < 4; cc++) {
            int c = cbase + cc;
            xout[gp * CCH + c] = xin[gp * CCH + c] + acc[cc][pp] * mv;
        }
    }
}

__global__ void __launch_bounds__(128) k_qkv(const float* __restrict__ xin,
                                             const float* __restrict__ lw, const float* __restrict__ lb,
                                             const float* __restrict__ qkvw) {
    __shared__ float ysh[32 * 64];
    __shared__ float Wsh[64 * 65];
    int tid = threadIdx.x;
    int b = blockIdx.x >> 7;
    int p0 = (blockIdx.x & 127) << 5;
    int warp = tid >> 5, lane = tid & 31;
    #pragma unroll
    for (int k = 0; k < 8; k++) {
        int pix = warp * 8 + k;
        size_t base = ((size_t)b * NPIX + p0 + pix) * CCH;
        float v0 = xin[base + lane], v1 = xin[base + lane + 32];
        float s = v0 + v1, sq = v0 * v0 + v1 * v1;
        #pragma unroll
        for (int o = 16; o > 0; o >>= 1) {
            s += __shfl_xor_sync(0xffffffffu, s, o);
            sq += __shfl_xor_sync(0xffffffffu, sq, o);
        }
        float mu = s * (1.f / 64.f);
        float rsg = rsqrtf(sq * (1.f / 64.f) - mu * mu + 1e-5f);
        ysh[pix * 64 + lane] = (v0 - mu) * rsg * lw[lane] + lb[lane];
        ysh[pix * 64 + lane + 32] = (v1 - mu) * rsg * lw[lane + 32] + lb[lane + 32];
    }
    int cg = tid & 15, pg = tid >> 4;
    int obase = cg * 4, pbase = pg * 4;
    float* outs[3] = {g_q, g_k, g_v};
    for (int ch = 0; ch < 3; ch++) {
        __syncthreads();
        #pragma unroll
        for (int i = 0; i < 32; i++) {
            int lin = tid + i * 128;
            Wsh[(lin & 63) * 65 + (lin >> 6)] = qkvw[(ch * 64 + (lin >> 6)) * 64 + (lin & 63)];
        }
        __syncthreads();
        float acc[4][4] = {};
        #pragma unroll 4
        for (int k = 0; k < 64; k++) {
            float w0 = Wsh[k * 65 + obase + 0];
            float w1 = Wsh[k * 65 + obase + 1];
            float w2 = Wsh[k * 65 + obase + 2];
            float w3 = Wsh[k * 65 + obase + 3];
            #pragma unroll
            for (int pp = 0; pp < 4; pp++) {
                float y = ysh[(pbase + pp) * 64 + k];
                acc[0][pp] = fmaf(w0, y, acc[0][pp]);
                acc[1][pp] = fmaf(w1, y, acc[1][pp]);
                acc[2][pp] = fmaf(w2, y, acc[2][pp]);
                acc[3][pp] = fmaf(w3, y, acc[3][pp]);
            }
        }
        float* op = outs[ch];
        #pragma unroll
        for (int pp = 0; pp < 4; pp++) {
            size_t base = ((size_t)b * NPIX + p0 + pbase + pp) * CCH;
            #pragma unroll
            for (int cc = 0; cc < 4; cc++) op[base + obase + cc] = acc[cc][pp];
        }
    }
}

__global__ void __launch_bounds__(128) k_attn(const float* __restrict__ xn,
                                              const float* __restrict__ outw,
                                              const float* __restrict__ outb) {
    __shared__ float sm2[64 * 61 * 2 + 32 * 65];
    float* ksh = sm2;
    float* vsh = sm2 + 64 * 61;
    float* osh = sm2 + 64 * 61 * 2;
    int tid = threadIdx.x;
    int b = blockIdx.x >> 7;
    int tile = blockIdx.x & 127;
    int tx0 = (tile & 7) << 3;
    int ty0 = (tile >> 3) << 2;
    #pragma unroll
    for (int i = 0; i < 30; i++) {
        int lin = tid + i * 128;
        int pos = lin >> 6, ch = lin & 63;
        int hy = pos / 10, hx = pos - hy * 10;
        int gy = ty0 + hy - 1, gx = tx0 + hx - 1;
        float kv = 0.f, vv = 0.f;
        if ((unsigned)gy < 64u && (unsigned)gx < 64u) {
            size_t a = ((size_t)b * NPIX + gy * 64 + gx) * CCH + ch;
            kv = g_k[a]; vv = g_v[a];
        }
        ksh[ch * 61 + pos] = kv;
        vsh[ch * 61 + pos] = vv;
    }
    __syncthreads();
    {
        int head = tid >> 5, lp = tid & 31;
        int py = lp >> 3, px = lp & 7;
        int gy = ty0 + py, gx = tx0 + px;
        size_t qbase = ((size_t)b * NPIX + gy * 64 + gx) * CCH + head * 16;
        float q[16];
        #pragma unroll
        for (int i = 0; i < 4; i++) {
            float4 t4 = *(const float4*)&g_q[qbase + i * 4];
            q[i * 4] = t4.x; q[i * 4 + 1] = t4.y; q[i * 4 + 2] = t4.z; q[i * 4 + 3] = t4.w;
        }
        float lg[9];
        #pragma unroll
        for (int t = 0; t < 9; t++) {
            int pos = (py + t / 3) * 10 + px + t % 3;
            float d = 0.f;
            #pragma unroll
            for (int i = 0; i < 16; i++) d = fmaf(q[i], ksh[(head * 16 + i) * 61 + pos], d);
            lg[t] = d * ATT_SCALE;
        }
        float m = lg[0];
        #pragma unroll
        for (int t = 1; t < 9; t++) m = fmaxf(m, lg[t]);
        float e[9], ssum = 0.f;
        #pragma unroll
        for (int t = 0; t < 9; t++) { e[t] = __expf(lg[t] - m); ssum += e[t]; }
        float inv = 1.f / ssum;
        float o[16] = {};
        #pragma unroll
        for (int t = 0; t < 9; t++) {
            int pos = (py + t / 3) * 10 + px + t % 3;
            float a = e[t] * inv;
            #pragma unroll
            for (int i = 0; i < 16; i++) o[i] = fmaf(a, vsh[(head * 16 + i) * 61 + pos], o[i]);
        }
        #pragma unroll
        for (int i = 0; i < 16; i++) osh[lp * 65 + head * 16 + i] = o[i];
    }
    __syncthreads();
    float* wsh = sm2;
    #pragma unroll
    for (int i = 0; i < 32; i++) {
        int lin = tid + i * 128;
        wsh[(lin & 63) * 65 + (lin >> 6)] = outw[(lin >> 6) * 64 + (lin & 63)];
    }
    __syncthreads();
    int cg = tid & 15, pg = tid >> 4;
    int cbase = cg * 4, pbase = pg * 4;
    float acc[4][4] = {};
    #pragma unroll 4
    for (int k = 0; k < 64; k++) {
        float w0 = wsh[k * 65 + cbase + 0];
        float w1 = wsh[k * 65 + cbase + 1];
        float w2 = wsh[k * 65 + cbase + 2];
        float w3 = wsh[k * 65 + cbase + 3];
        #pragma unroll
        for (int pp = 0; pp < 4; pp++) {
            float ov = osh[(pbase + pp) * 65 + k];
            acc[0][pp] = fmaf(w0, ov, acc[0][pp]);
            acc[1][pp] = fmaf(w1, ov, acc[1][pp]);
            acc[2][pp] = fmaf(w2, ov, acc[2][pp]);
            acc[3][pp] = fmaf(w3, ov, acc[3][pp]);
        }
    }
    #pragma unroll
    for (int pp = 0; pp < 4; pp++) {
        int lp2 = pbase + pp;
        int gp = (ty0 + (lp2 >> 3)) * 64 + tx0 + (lp2 & 7);
        size_t base = ((size_t)b * NPIX + gp) * CCH;
        #pragma unroll
        for (int cc = 0; cc < 4; cc++) {
            int c = cbase + cc;
            g_t[base + c] = acc[cc][pp] + outb[c] + xn[base + c];
        }
    }
}

__global__ void __launch_bounds__(128) k_ff(const float* __restrict__ xprev,
                                            const float* __restrict__ lw, const float* __restrict__ lb,
                                            const float* __restrict__ w1, const float* __restrict__ b1,
                                            const float* __restrict__ w2, const float* __restrict__ b2,
                                            float* __restrict__ xout) {
    __shared__ float tsh[16 * 64];
    __shared__ float ysh[16 * 64];
    __shared__ float hsh[16 * 64];
    __shared__ float Wsh[64 * 65];
    int tid = threadIdx.x;
    int b = blockIdx.x >> 8;
    int p0 = (blockIdx.x & 255) << 4;
    #pragma unroll
    for (int i = 0; i < 8; i++) {
        int lin = tid + i * 128;
        tsh[lin] = g_t[((size_t)b * NPIX + p0) * CCH + lin];
    }
    __syncthreads();
    int warp = tid >> 5, lane = tid & 31;
    #pragma unroll
    for (int k = 0; k < 4; k++) {
        int pix = warp * 4 + k;
        float v0 = tsh[pix * 64 + lane], v1 = tsh[pix * 64 + lane + 32];
        float s = v0 + v1, sq = v0 * v0 + v1 * v1;
        #pragma unroll
        for (int o = 16; o > 0; o >>= 1) {
            s += __shfl_xor_sync(0xffffffffu, s, o);
            sq += __shfl_xor_sync(0xffffffffu, sq, o);
        }
        float mu = s * (1.f / 64.f);
        float rsg = rsqrtf(sq * (1.f / 64.f) - mu * mu + 1e-5f);
        ysh[pix * 64 + lane] = (v0 - mu) * rsg * lw[lane] + lb[lane];
        ysh[pix * 64 + lane + 32] = (v1 - mu) * rsg * lw[lane + 32] + lb[lane + 32];
    }
    __syncthreads();
    #pragma unroll
    for (int i = 0; i < 32; i++) {
        int lin = tid + i * 128;
        Wsh[(lin & 63) * 65 + (lin >> 6)] = w1[(lin >> 6) * 64 + (lin & 63)];
    }
    __syncthreads();
    int cg = tid & 15, pg = tid >> 4;
    int cbase = cg * 4, pbase = pg * 2;
    {
        float acc[4][2] = {};
        #pragma unroll 4
        for (int k = 0; k < 64; k++) {
            float w0 = Wsh[k * 65 + cbase + 0];
            float w1v = Wsh[k * 65 + cbase + 1];
            float w2v = Wsh[k * 65 + cbase + 2];
            float w3v = Wsh[k * 65 + cbase + 3];
            #pragma unroll
            for (int pp = 0; pp < 2; pp++) {
                float y = ysh[(pbase + pp) * 64 + k];
                acc[0][pp] = fmaf(w0, y, acc[0][pp]);
                acc[1][pp] = fmaf(w1v, y, acc[1][pp]);
                acc[2][pp] = fmaf(w2v, y, acc[2][pp]);
                acc[3][pp] = fmaf(w3v, y, acc[3][pp]);
            }
        }
        #pragma unroll
        for (int pp = 0; pp < 2; pp++)
            #pragma unroll
            for (int cc = 0; cc < 4; cc++) {
                float h = acc[cc][pp] + b1[cbase + cc];
                hsh[(pbase + pp) * 64 + cbase + cc] = 0.5f * h * (1.f + erff(h * 0.70710678118654752f));
            }
    }
    __syncthreads();
    #pragma unroll
    for (int i = 0; i < 32; i++) {
        int lin = tid + i * 128;
        Wsh[(lin & 63) * 65 + (lin >> 6)] = w2[(lin >> 6) * 64 + (lin & 63)];
    }
    __syncthreads();
    {
        float acc[4][2] = {};
        #pragma unroll 4
        for (int k = 0; k < 64; k++) {
            float w0 = Wsh[k * 65 + cbase + 0];
            float w1v = Wsh[k * 65 + cbase + 1];
            float w2v = Wsh[k * 65 + cbase + 2];
            float w3v = Wsh[k * 65 + cbase + 3];
            #pragma unroll
            for (int pp = 0; pp < 2; pp++) {
                float y = hsh[(pbase + pp) * 64 + k];
                acc[0][pp] = fmaf(w0, y, acc[0][pp]);
                acc[1][pp] = fmaf(w1v, y, acc[1][pp]);
                acc[2][pp] = fmaf(w2v, y, acc[2][pp]);
                acc[3][pp] = fmaf(w3v, y, acc[3][pp]);
            }
        }
        #pragma unroll
        for (int pp = 0; pp < 2; pp++) {
            int lpix = pbase + pp;
            size_t base = ((size_t)b * NPIX + p0 + lpix) * CCH;
            #pragma unroll
            for (int cc = 0; cc < 4; cc++) {
                int c = cbase + cc;
                float val = acc[cc][pp] + b2[c] + tsh[lpix * 64 + c];
                if (c == 0) val = xprev[base];
                xout[base + c] = val;
            }
        }
    }
}

extern "C" void kernel_launch(void* const* d_in, const int* in_sizes, int n_in,
                              void* d_out, int out_size) {
    const float* x = (const float*)d_in[0];
    const void* masks = d_in[1];
    const float* p0_w = (const float*)d_in[2];
    const float* p0_b = (const float*)d_in[3];
    const float* p1_w = (const float*)d_in[4];
    const float* p1_b = (const float*)d_in[5];
    const float* fc0_w = (const float*)d_in[6];
    const float* fc0_b = (const float*)d_in[7];
    const float* fc1_w = (const float*)d_in[8];
    const float* n0w = (const float*)d_in[9];
    const float* n0b = (const float*)d_in[10];
    const float* ln1w = (const float*)d_in[11];
    const float* ln1b = (const float*)d_in[12];
    const float* qkvw = (const float*)d_in[13];
    const float* outw = (const float*)d_in[14];
    const float* outb = (const float*)d_in[15];
    const float* ln2w = (const float*)d_in[16];
    const float* ln2b = (const float*)d_in[17];
    const float* ff1w = (const float*)d_in[18];
    const float* ff1b = (const float*)d_in[19];
    const float* ff2w = (const float*)d_in[20];
    const float* ff2b = (const float*)d_in[21];
    float* out = (float*)d_out;

    cudaFuncSetAttribute(k_conv_mma, cudaFuncAttributeMaxDynamicSharedMemorySize,
                         CONV_SMEM_BYTES);

    k_fold<<<288, 256>>>(fc0_w, fc0_b, p0_w, p0_b, p1_w, p1_b);
    k_maskdetect<<<1, 1024>>>((const unsigned char*)masks, 6 * BATCH * NPIX);

    void* sym = nullptr;
    cudaGetSymbolAddress(&sym, g_xbuf);
    float* buf0 = (float*)sym;
    float* buf1 = buf0 + BATCH * NPIX * CCH;

    const float* cur = x;
    for (int s = 0; s < 6; s++) {
        float* stage = (s & 1) ? buf1 : buf0;
        float* nxt = (s == 5) ? out : stage;
        k_conv_mma<<<256, 256, CONV_SMEM_BYTES>>>(cur);
        k_stats<<<8, 32>>>();
        k_fc1<<<1024, 128>>>(cur, n0w, n0b, fc1_w, masks, s, stage);
        k_qkv<<<1024, 128>>>(stage, ln1w, ln1b, qkvw);
        k_attn<<<1024, 128>>>(stage, outw, outb);
        k_ff<<<2048, 128>>>(cur, ln2w, ln2b, ff1w, ff1b, ff2w, ff2b, nxt);
        cur = nxt;
    }
}

// round 8
// speedup vs baseline: 1.5665x; 1.2121x over previous
#include <cuda_runtime.h>
#include <math.h>
#include <stdint.h>

#define BATCH 8
#define NPIX 4096
#define CCH 64
#define HID 128
#define ATT_SCALE 0.25f

static __device__ float g_Wswz[9 * 128 * 64];    // pre-swizzled tf32 conv weights [tap][o][64]
static __device__ float g_QKVswz[192 * 64];      // pre-swizzled tf32 qkv weights [o][64]
static __device__ float g_FC1swz[64 * 128];      // pre-swizzled tf32 fc1 weights [o][128]
static __device__ float g_beff[HID];
static __device__ float g_xbuf[2][BATCH * NPIX * CCH];
static __device__ float g_hd[BATCH * NPIX * HID];
static __device__ float g_part[256 * 2];
static __device__ float g_q[BATCH * NPIX * CCH];
static __device__ float g_k[BATCH * NPIX * CCH];
static __device__ float g_v[BATCH * NPIX * CCH];
static __device__ float g_t[BATCH * NPIX * CCH];
static __device__ int g_maskmode;

__device__ __forceinline__ uint32_t f2tf32(float f) {
    uint32_t u;
    asm("cvt.rna.tf32.f32 %0, %1;" : "=r"(u) : "f"(f));
    return u;
}

// swizzled chunk index for channel/k index c within a 64-float row of parity par
__device__ __forceinline__ int swz_pos(int c, int par) {
    int t4 = c & 3, idx = c >> 2;
    int pi = (t4 * 4 + (((idx >> 2) + t4) & 3)) ^ par;
    return pi * 4 + (idx & 3);
}

__global__ void k_maskdetect(const unsigned char* m, int nbytes) {
    __shared__ int hasBig, hasMis;
    if (threadIdx.x == 0) { hasBig = 0; hasMis = 0; }
    __syncthreads();
    for (int i = threadIdx.x; i < nbytes; i += blockDim.x) {
        unsigned char v = m[i];
        if (v > 1) hasBig = 1;
        else if (v && (i & 3)) hasMis = 1;
    }
    __syncthreads();
    if (threadIdx.x == 0) g_maskmode = (!hasBig && hasMis) ? 1 : 0;
}

__global__ void k_fold(const float* __restrict__ fc0_w, const float* __restrict__ fc0_b,
                       const float* __restrict__ p0_w, const float* __restrict__ p0_b,
                       const float* __restrict__ p1_w, const float* __restrict__ p1_b) {
    int t = blockIdx.x * 256 + threadIdx.x;
    if (t >= HID * 576) return;
    int o = t / 576, k = t - o * 576;
    int tap = k >> 6, c = k & 63;
    const float* f1 = fc0_w + o * 192 + 64;
    const float* f2 = fc0_w + o * 192 + 128;
    float acc = 0.f;
    for (int m = 0; m < 64; m++) {
        acc = fmaf(f1[m], p0_w[(m * 64 + c) * 9 + tap], acc);
        acc = fmaf(f2[m], p1_w[(m * 64 + c) * 9 + tap], acc);
    }
    if (tap == 4) acc += fc0_w[o * 192 + c];
    g_Wswz[(tap * 128 + o) * 64 + swz_pos(c, o & 1)] = __uint_as_float(f2tf32(acc));
    if (k == 0) {
        float b = fc0_b[o];
        for (int m = 0; m < 64; m++) {
            b = fmaf(f1[m], p0_b[m], b);
            b = fmaf(f2[m], p1_b[m], b);
        }
        g_beff[o] = b;
    }
}

// pre-swizzle qkv + fc1 weights (tf32)
__global__ void k_prepw(const float* __restrict__ qkvw, const float* __restrict__ fc1w) {
    int t = blockIdx.x * 256 + threadIdx.x;
    if (t < 192 * 64) {
        int o = t >> 6, k = t & 63;
        g_QKVswz[o * 64 + swz_pos(k, o & 1)] = __uint_as_float(f2tf32(qkvw[t]));
    }
    if (t < 64 * 128) {
        int o = t >> 7, k = t & 127;
        int half = k >> 6, kk = k & 63;
        g_FC1swz[o * 128 + half * 64 + swz_pos(kk, o & 1)] = __uint_as_float(f2tf32(fc1w[t]));
    }
}

__device__ __forceinline__ int refl(int v) { return v < 0 ? -v : (v > 63 ? 126 - v : v); }

__device__ __forceinline__ void mma_tf32(float* c, const uint32_t* a, uint32_t b0, uint32_t b1) {
    asm volatile(
        "mma.sync.aligned.m16n8k8.row.col.f32.tf32.tf32.f32 "
        "{%0,%1,%2,%3}, {%4,%5,%6,%7}, {%8,%9}, {%0,%1,%2,%3};"
        : "+f"(c[0]), "+f"(c[1]), "+f"(c[2]), "+f"(c[3])
        : "r"(a[0]), "r"(a[1]), "r"(a[2]), "r"(a[3]), "r"(b0), "r"(b1));
}

// ---------------- tensor-core conv: 128 pix x 128 out per block ----------------
#define XH_FLOATS (264 * 64)
#define W_FLOATS (128 * 64)
#define CONV_SMEM_BYTES ((XH_FLOATS + W_FLOATS) * 4)

__global__ void __launch_bounds__(256, 2) k_conv_mma(const float* __restrict__ xin) {
    extern __shared__ float sm[];
    float* Xh = sm;
    float* Wsh = sm + XH_FLOATS;
    int tid = threadIdx.x;
    int batch = blockIdx.x >> 5;
    int y0 = (blockIdx.x & 31) << 1;
    const float* xb = xin + (size_t)batch * NPIX * CCH;

    #pragma unroll 2
    for (int i = 0; i < 66; i++) {
        int lin = i * 256 + tid;
        int ch = lin & 63;
        int hp = lin >> 6;
        int hr = hp / 66, hc = hp - hr * 66;
        int gy = refl(y0 + hr - 1), gx = refl(hc - 1);
        float v = xb[(gy * 64 + gx) * CCH + ch];
        Xh[hp * 64 + swz_pos(ch, hp & 1)] = __uint_as_float(f2tf32(v));
    }

    int warp = tid >> 5, lane = tid & 31;
    int g = lane >> 2, t4 = lane & 3;
    int pixBase = (warp >> 1) * 32;
    int nBase = (warp & 1) * 64;

    float acc[2][8][4];
    #pragma unroll
    for (int m = 0; m < 2; m++)
        #pragma unroll
        for (int n = 0; n < 8; n++)
            #pragma unroll
            for (int j2 = 0; j2 < 4; j2++) acc[m][n][j2] = 0.f;

    for (int tap = 0; tap < 9; tap++) {
        int dy = tap / 3, dx = tap - dy * 3;
        __syncthreads();
        {
            const float4* wsrc = (const float4*)(g_Wswz + tap * (128 * 64));
            float4* wdst = (float4*)Wsh;
            #pragma unroll
            for (int i = 0; i < 8; i++) wdst[i * 256 + tid] = wsrc[i * 256 + tid];
        }
        __syncthreads();

        #pragma unroll
        for (int j = 0; j < 4; j++) {
            int pibase = t4 * 4 + ((j + t4) & 3);
            float4 av[4];
            #pragma unroll
            for (int r = 0; r < 4; r++) {
                int pr = pixBase + r * 8 + g;
                int hb = ((pr >> 6) + dy) * 66 + (pr & 63) + dx;
                av[r] = *(const float4*)&Xh[hb * 64 + ((pibase ^ (hb & 1)) << 2)];
            }
            uint32_t aH0m0[4] = {__float_as_uint(av[0].x), __float_as_uint(av[1].x),
                                 __float_as_uint(av[0].y), __float_as_uint(av[1].y)};
            uint32_t aH1m0[4] = {__float_as_uint(av[0].z), __float_as_uint(av[1].z),
                                 __float_as_uint(av[0].w), __float_as_uint(av[1].w)};
            uint32_t aH0m1[4] = {__float_as_uint(av[2].x), __float_as_uint(av[3].x),
                                 __float_as_uint(av[2].y), __float_as_uint(av[3].y)};
            uint32_t aH1m1[4] = {__float_as_uint(av[2].z), __float_as_uint(av[3].z),
                                 __float_as_uint(av[2].w), __float_as_uint(av[3].w)};
            #pragma unroll
            for (int n = 0; n < 8; n++) {
                int o = nBase + n * 8 + g;
                float4 bv = *(const float4*)&Wsh[o * 64 + ((pibase ^ (o & 1)) << 2)];
                uint32_t b0 = __float_as_uint(bv.x), b1 = __float_as_uint(bv.y);
                uint32_t b2 = __float_as_uint(bv.z), b3 = __float_as_uint(bv.w);
                mma_tf32(acc[0][n], aH0m0, b0, b1);
                mma_tf32(acc[0][n], aH1m0, b2, b3);
                mma_tf32(acc[1][n], aH0m1, b0, b1);
                mma_tf32(acc[1][n], aH1m1, b2, b3);
            }
        }
    }
    __syncthreads();

    float s = 0.f, sq = 0.f;
    #pragma unroll
    for (int m = 0; m < 2; m++) {
        int p_lo = pixBase + m * 16 + g;
        int p_hi = p_lo + 8;
        size_t row_lo = ((size_t)batch * NPIX + y0 * 64 + p_lo) * HID;
        size_t row_hi = ((size_t)batch * NPIX + y0 * 64 + p_hi) * HID;
        #pragma unroll
        for (int n = 0; n < 8; n++) {
            int col = nBase + n * 8 + 2 * t4;
            float bo0 = g_beff[col], bo1 = g_beff[col + 1];
            float r0 = fmaxf(acc[m][n][0] + bo0, 0.f);
            float r1 = fmaxf(acc[m][n][1] + bo1, 0.f);
            float r2 = fmaxf(acc[m][n][2] + bo0, 0.f);
            float r3 = fmaxf(acc[m][n][3] + bo1, 0.f);
            *(float2*)&g_hd[row_lo + col] = make_float2(r0, r1);
            *(float2*)&g_hd[row_hi + col] = make_float2(r2, r3);
            s += r0 + r1 + r2 + r3;
            sq += r0 * r0 + r1 * r1 + r2 * r2 + r3 * r3;
        }
    }
    float* red = sm;
    red[tid] = s; red[256 + tid] = sq;
    __syncthreads();
    for (int st = 128; st > 0; st >>= 1) {
        if (tid < st) { red[tid] += red[tid + st]; red[256 + tid] += red[256 + tid + st]; }
        __syncthreads();
    }
    if (tid == 0) { g_part[blockIdx.x * 2] = red[0]; g_part[blockIdx.x * 2 + 1] = red[256]; }
}

// ---------------- fc1 via tf32 MMA: 64 px x 64 out x K128, fused stats reduce ----------------
#define FC1_SMEM_BYTES ((64 * 128 + 64 * 128) * 4)

__global__ void __launch_bounds__(256, 2) k_fc1_mma(const float* __restrict__ xin,
                                                    const float* __restrict__ nw,
                                                    const float* __restrict__ nb,
                                                    const void* __restrict__ mask, int s,
                                                    float* __restrict__ xout) {
    extern __shared__ float sm[];
    float* ysh = sm;                  // [64][128] swizzled halves
    float* Wsh = sm + 64 * 128;       // [64][128] swizzled halves
    __shared__ float s_mu, s_rs;
    int tid = threadIdx.x;
    int b = blockIdx.x >> 6;
    int p0 = (blockIdx.x & 63) << 6;

    // fused per-batch global LN stats
    if (tid < 32) {
        float ss = g_part[(b * 32 + tid) * 2];
        float sq = g_part[(b * 32 + tid) * 2 + 1];
        #pragma unroll
        for (int o = 16; o > 0; o >>= 1) {
            ss += __shfl_xor_sync(0xffffffffu, ss, o);
            sq += __shfl_xor_sync(0xffffffffu, sq, o);
        }
        if (tid == 0) {
            const float inv = 1.f / 524288.f;
            float mu = ss * inv;
            s_mu = mu;
            s_rs = rsqrtf(sq * inv - mu * mu + 1e-5f);
        }
    }
    // stage weights (independent of stats)
    {
        const float4* wsrc = (const float4*)g_FC1swz;
        float4* wdst = (float4*)Wsh;
        #pragma unroll
        for (int i = 0; i < 8; i++) wdst[i * 256 + tid] = wsrc[i * 256 + tid];
    }
    __syncthreads();
    float mu = s_mu, rs = s_rs;

    // stage normalized activations, tf32 swizzled
    #pragma unroll
    for (int i = 0; i < 32; i++) {
        int lin = i * 256 + tid;
        int pix = lin >> 7, kk = lin & 127;
        size_t gi = ((size_t)b * NPIX + p0 + pix) * HID + kk;
        int ii = (p0 + pix) * HID + kk;
        float y = (g_hd[gi] - mu) * rs * nw[ii] + nb[ii];
        int half = kk >> 6, kc = kk & 63;
        ysh[pix * 128 + half * 64 + swz_pos(kc, pix & 1)] = __uint_as_float(f2tf32(y));
    }
    __syncthreads();

    int warp = tid >> 5, lane = tid & 31;
    int g = lane >> 2, t4 = lane & 3;
    int pixBase = (warp & 1) * 32;
    int oBase = (warp >> 1) * 16;

    float acc[2][2][4];
    #pragma unroll
    for (int m = 0; m < 2; m++)
        #pragma unroll
        for (int n = 0; n < 2; n++)
            #pragma unroll
            for (int j = 0; j < 4; j++) acc[m][n][j] = 0.f;

    #pragma unroll
    for (int half = 0; half < 2; half++) {
        #pragma unroll
        for (int j = 0; j < 4; j++) {
            int pibase = t4 * 4 + ((j + t4) & 3);
            float4 av[4];
            #pragma unroll
            for (int r = 0; r < 4; r++) {
                int pr = pixBase + r * 8 + g;
                av[r] = *(const float4*)&ysh[pr * 128 + half * 64 + ((pibase ^ (pr & 1)) << 2)];
            }
            uint32_t aH0m0[4] = {__float_as_uint(av[0].x), __float_as_uint(av[1].x),
                                 __float_as_uint(av[0].y), __float_as_uint(av[1].y)};
            uint32_t aH1m0[4] = {__float_as_uint(av[0].z), __float_as_uint(av[1].z),
                                 __float_as_uint(av[0].w), __float_as_uint(av[1].w)};
            uint32_t aH0m1[4] = {__float_as_uint(av[2].x), __float_as_uint(av[3].x),
                                 __float_as_uint(av[2].y), __float_as_uint(av[3].y)};
            uint32_t aH1m1[4] = {__float_as_uint(av[2].z), __float_as_uint(av[3].z),
                                 __float_as_uint(av[2].w), __float_as_uint(av[3].w)};
            #pragma unroll
            for (int n = 0; n < 2; n++) {
                int o = oBase + n * 8 + g;
                float4 bv = *(const float4*)&Wsh[o * 128 + half * 64 + ((pibase ^ (o & 1)) << 2)];
                uint32_t b0 = __float_as_uint(bv.x), b1 = __float_as_uint(bv.y);
                uint32_t b2 = __float_as_uint(bv.z), b3 = __float_as_uint(bv.w);
                mma_tf32(acc[0][n], aH0m0, b0, b1);
                mma_tf32(acc[0][n], aH1m0, b2, b3);
                mma_tf32(acc[1][n], aH0m1, b0, b1);
                mma_tf32(acc[1][n], aH1m1, b2, b3);
            }
        }
    }

    int mode = g_maskmode;
    #pragma unroll
    for (int m = 0; m < 2; m++) {
        int p_lo = pixBase + m * 16 + g;
        int p_hi = p_lo + 8;
        size_t gplo = (size_t)b * NPIX + p0 + p_lo;
        size_t gphi = (size_t)b * NPIX + p0 + p_hi;
        size_t milo = (size_t)s * 32768 + gplo;
        size_t mihi = (size_t)s * 32768 + gphi;
        float mvlo, mvhi;
        if (mode) {
            mvlo = ((const unsigned char*)mask)[milo] ? 1.f : 0.f;
            mvhi = ((const unsigned char*)mask)[mihi] ? 1.f : 0.f;
        } else {
            mvlo = ((const unsigned int*)mask)[milo] ? 1.f : 0.f;
            mvhi = ((const unsigned int*)mask)[mihi] ? 1.f : 0.f;
        }
        #pragma unroll
        for (int n = 0; n < 2; n++) {
            int col = oBase + n * 8 + 2 * t4;
            float2 x0 = *(const float2*)&xin[gplo * CCH + col];
            float2 x1 = *(const float2*)&xin[gphi * CCH + col];
            float2 o0 = make_float2(x0.x + acc[m][n][0] * mvlo, x0.y + acc[m][n][1] * mvlo);
            float2 o1 = make_float2(x1.x + acc[m][n][2] * mvhi, x1.y + acc[m][n][3] * mvhi);
            *(float2*)&xout[gplo * CCH + col] = o0;
            *(float2*)&xout[gphi * CCH + col] = o1;
        }
    }
}

// ---------------- qkv via tf32 MMA: 64 px x 192 out x K64 ----------------
#define QKV_SMEM_BYTES ((64 * 64 + 192 * 64) * 4)

__global__ void __launch_bounds__(256, 2) k_qkv_mma(const float* __restrict__ xin,
                                                    const float* __restrict__ lw,
                                                    const float* __restrict__ lb) {
    extern __shared__ float sm[];
    float* ysh = sm;                 // [64][64] swizzled
    float* Wsh = sm + 64 * 64;       // [192][64] swizzled
    int tid = threadIdx.x;
    int b = blockIdx.x >> 6;
    int p0 = (blockIdx.x & 63) << 6;
    int warp = tid >> 5, lane = tid & 31;

    // LN prologue: each warp 8 pixels
    #pragma unroll
    for (int k = 0; k < 8; k++) {
        int pix = warp * 8 + k;
        size_t base = ((size_t)b * NPIX + p0 + pix) * CCH;
        float v0 = xin[base + lane], v1 = xin[base + lane + 32];
        float s = v0 + v1, sq = v0 * v0 + v1 * v1;
        #pragma unroll
        for (int o = 16; o > 0; o >>= 1) {
            s += __shfl_xor_sync(0xffffffffu, s, o);
            sq += __shfl_xor_sync(0xffffffffu, sq, o);
        }
        float mu = s * (1.f / 64.f);
        float rsg = rsqrtf(sq * (1.f / 64.f) - mu * mu + 1e-5f);
        float y0 = (v0 - mu) * rsg * lw[lane] + lb[lane];
        float y1 = (v1 - mu) * rsg * lw[lane + 32] + lb[lane + 32];
        ysh[pix * 64 + swz_pos(lane, pix & 1)] = __uint_as_float(f2tf32(y0));
        ysh[pix * 64 + swz_pos(lane + 32, pix & 1)] = __uint_as_float(f2tf32(y1));
    }
    // stage weights: 12288 floats = 3072 float4
    {
        const float4* wsrc = (const float4*)g_QKVswz;
        float4* wdst = (float4*)Wsh;
        #pragma unroll
        for (int i = 0; i < 12; i++) wdst[i * 256 + tid] = wsrc[i * 256 + tid];
    }
    __syncthreads();

    int g = lane >> 2, t4 = lane & 3;
    int pixBase = (warp & 1) * 32;
    int oBase = (warp >> 1) * 48;

    float acc[2][6][4];
    #pragma unroll
    for (int m = 0; m < 2; m++)
        #pragma unroll
        for (int n = 0; n < 6; n++)
            #pragma unroll
            for (int j = 0; j < 4; j++) acc[m][n][j] = 0.f;

    #pragma unroll
    for (int j = 0; j < 4; j++) {
        int pibase = t4 * 4 + ((j + t4) & 3);
        float4 av[4];
        #pragma unroll
        for (int r = 0; r < 4; r++) {
            int pr = pixBase + r * 8 + g;
            av[r] = *(const float4*)&ysh[pr * 64 + ((pibase ^ (pr & 1)) << 2)];
        }
        uint32_t aH0m0[4] = {__float_as_uint(av[0].x), __float_as_uint(av[1].x),
                             __float_as_uint(av[0].y), __float_as_uint(av[1].y)};
        uint32_t aH1m0[4] = {__float_as_uint(av[0].z), __float_as_uint(av[1].z),
                             __float_as_uint(av[0].w), __float_as_uint(av[1].w)};
        uint32_t aH0m1[4] = {__float_as_uint(av[2].x), __float_as_uint(av[3].x),
                             __float_as_uint(av[2].y), __float_as_uint(av[3].y)};
        uint32_t aH1m1[4] = {__float_as_uint(av[2].z), __float_as_uint(av[3].z),
                             __float_as_uint(av[2].w), __float_as_uint(av[3].w)};
        #pragma unroll
        for (int n = 0; n < 6; n++) {
            int o = oBase + n * 8 + g;
            float4 bv = *(const float4*)&Wsh[o * 64 + ((pibase ^ (o & 1)) << 2)];
            uint32_t b0 = __float_as_uint(bv.x), b1 = __float_as_uint(bv.y);
            uint32_t b2 = __float_as_uint(bv.z), b3 = __float_as_uint(bv.w);
            mma_tf32(acc[0][n], aH0m0, b0, b1);
            mma_tf32(acc[0][n], aH1m0, b2, b3);
            mma_tf32(acc[1][n], aH0m1, b0, b1);
            mma_tf32(acc[1][n], aH1m1, b2, b3);
        }
    }

    #pragma unroll
    for (int m = 0; m < 2; m++) {
        int p_lo = pixBase + m * 16 + g;
        int p_hi = p_lo + 8;
        size_t gplo = (size_t)b * NPIX + p0 + p_lo;
        size_t gphi = (size_t)b * NPIX + p0 + p_hi;
        #pragma unroll
        for (int n = 0; n < 6; n++) {
            int col = oBase + n * 8 + 2 * t4;
            int region = col >> 6;
            int c = col & 63;
            float* dst = (region == 0) ? g_q : (region == 1) ? g_k : g_v;
            *(float2*)&dst[gplo * CCH + c] = make_float2(acc[m][n][0], acc[m][n][1]);
            *(float2*)&dst[gphi * CCH + c] = make_float2(acc[m][n][2], acc[m][n][3]);
        }
    }
}

__global__ void __launch_bounds__(128) k_attn(const float* __restrict__ xn,
                                              const float* __restrict__ outw,
                                              const float* __restrict__ outb) {
    __shared__ float sm2[64 * 61 * 2 + 32 * 65];
    float* ksh = sm2;
    float* vsh = sm2 + 64 * 61;
    float* osh = sm2 + 64 * 61 * 2;
    int tid = threadIdx.x;
    int b = blockIdx.x >> 7;
    int tile = blockIdx.x & 127;
    int tx0 = (tile & 7) << 3;
    int ty0 = (tile >> 3) << 2;
    #pragma unroll
    for (int i = 0; i < 30; i++) {
        int lin = tid + i * 128;
        int pos = lin >> 6, ch = lin & 63;
        int hy = pos / 10, hx = pos - hy * 10;
        int gy = ty0 + hy - 1, gx = tx0 + hx - 1;
        float kv = 0.f, vv = 0.f;
        if ((unsigned)gy < 64u && (unsigned)gx < 64u) {
            size_t a = ((size_t)b * NPIX + gy * 64 + gx) * CCH + ch;
            kv = g_k[a]; vv = g_v[a];
        }
        ksh[ch * 61 + pos] = kv;
        vsh[ch * 61 + pos] = vv;
    }
    __syncthreads();
    {
        int head = tid >> 5, lp = tid & 31;
        int py = lp >> 3, px = lp & 7;
        int gy = ty0 + py, gx = tx0 + px;
        size_t qbase = ((size_t)b * NPIX + gy * 64 + gx) * CCH + head * 16;
        float q[16];
        #pragma unroll
        for (int i = 0; i < 4; i++) {
            float4 t4 = *(const float4*)&g_q[qbase + i * 4];
            q[i * 4] = t4.x; q[i * 4 + 1] = t4.y; q[i * 4 + 2] = t4.z; q[i * 4 + 3] = t4.w;
        }
        float lg[9];
        #pragma unroll
        for (int t = 0; t < 9; t++) {
            int pos = (py + t / 3) * 10 + px + t % 3;
            float d = 0.f;
            #pragma unroll
            for (int i = 0; i < 16; i++) d = fmaf(q[i], ksh[(head * 16 + i) * 61 + pos], d);
            lg[t] = d * ATT_SCALE;
        }
        float m = lg[0];
        #pragma unroll
        for (int t = 1; t < 9; t++) m = fmaxf(m, lg[t]);
        float e[9], ssum = 0.f;
        #pragma unroll
        for (int t = 0; t < 9; t++) { e[t] = __expf(lg[t] - m); ssum += e[t]; }
        float inv = 1.f / ssum;
        float o[16] = {};
        #pragma unroll
        for (int t = 0; t < 9; t++) {
            int pos = (py + t / 3) * 10 + px + t % 3;
            float a = e[t] * inv;
            #pragma unroll
            for (int i = 0; i < 16; i++) o[i] = fmaf(a, vsh[(head * 16 + i) * 61 + pos], o[i]);
        }
        #pragma unroll
        for (int i = 0; i < 16; i++) osh[lp * 65 + head * 16 + i] = o[i];
    }
    __syncthreads();
    float* wsh = sm2;
    #pragma unroll
    for (int i = 0; i < 32; i++) {
        int lin = tid + i * 128;
        wsh[(lin & 63) * 65 + (lin >> 6)] = outw[(lin >> 6) * 64 + (lin & 63)];
    }
    __syncthreads();
    int cg = tid & 15, pg = tid >> 4;
    int cbase = cg * 4, pbase = pg * 4;
    float acc[4][4] = {};
    #pragma unroll 4
    for (int k = 0; k < 64; k++) {
        float w0 = wsh[k * 65 + cbase + 0];
        float w1 = wsh[k * 65 + cbase + 1];
        float w2 = wsh[k * 65 + cbase + 2];
        float w3 = wsh[k * 65 + cbase + 3];
        #pragma unroll
        for (int pp = 0; pp < 4; pp++) {
            float ov = osh[(pbase + pp) * 65 + k];
            acc[0][pp] = fmaf(w0, ov, acc[0][pp]);
            acc[1][pp] = fmaf(w1, ov, acc[1][pp]);
            acc[2][pp] = fmaf(w2, ov, acc[2][pp]);
            acc[3][pp] = fmaf(w3, ov, acc[3][pp]);
        }
    }
    #pragma unroll
    for (int pp = 0; pp < 4; pp++) {
        int lp2 = pbase + pp;
        int gp = (ty0 + (lp2 >> 3)) * 64 + tx0 + (lp2 & 7);
        size_t base = ((size_t)b * NPIX + gp) * CCH;
        #pragma unroll
        for (int cc = 0; cc < 4; cc++) {
            int c = cbase + cc;
            g_t[base + c] = acc[cc][pp] + outb[c] + xn[base + c];
        }
    }
}

__global__ void __launch_bounds__(128) k_ff(const float* __restrict__ xprev,
                                            const float* __restrict__ lw, const float* __restrict__ lb,
                                            const float* __restrict__ w1, const float* __restrict__ b1,
                                            const float* __restrict__ w2, const float* __restrict__ b2,
                                            float* __restrict__ xout) {
    __shared__ float tsh[16 * 64];
    __shared__ float ysh[16 * 64];
    __shared__ float hsh[16 * 64];
    __shared__ float Wsh[64 * 65];
    int tid = threadIdx.x;
    int b = blockIdx.x >> 8;
    int p0 = (blockIdx.x & 255) << 4;
    #pragma unroll
    for (int i = 0; i < 8; i++) {
        int lin = tid + i * 128;
        tsh[lin] = g_t[((size_t)b * NPIX + p0) * CCH + lin];
    }
    __syncthreads();
    int warp = tid >> 5, lane = tid & 31;
    #pragma unroll
    for (int k = 0; k < 4; k++) {
        int pix = warp * 4 + k;
        float v0 = tsh[pix * 64 + lane], v1 = tsh[pix * 64 + lane + 32];
        float s = v0 + v1, sq = v0 * v0 + v1 * v1;
        #pragma unroll
        for (int o = 16; o > 0; o >>= 1) {
            s += __shfl_xor_sync(0xffffffffu, s, o);
            sq += __shfl_xor_sync(0xffffffffu, sq, o);
        }
        float mu = s * (1.f / 64.f);
        float rsg = rsqrtf(sq * (1.f / 64.f) - mu * mu + 1e-5f);
        ysh[pix * 64 + lane] = (v0 - mu) * rsg * lw[lane] + lb[lane];
        ysh[pix * 64 + lane + 32] = (v1 - mu) * rsg * lw[lane + 32] + lb[lane + 32];
    }
    __syncthreads();
    #pragma unroll
    for (int i = 0; i < 32; i++) {
        int lin = tid + i * 128;
        Wsh[(lin & 63) * 65 + (lin >> 6)] = w1[(lin >> 6) * 64 + (lin & 63)];
    }
    __syncthreads();
    int cg = tid & 15, pg = tid >> 4;
    int cbase = cg * 4, pbase = pg * 2;
    {
        float acc[4][2] = {};
        #pragma unroll 4
        for (int k = 0; k < 64; k++) {
            float w0 = Wsh[k * 65 + cbase + 0];
            float w1v = Wsh[k * 65 + cbase + 1];
            float w2v = Wsh[k * 65 + cbase + 2];
            float w3v = Wsh[k * 65 + cbase + 3];
            #pragma unroll
            for (int pp = 0; pp < 2; pp++) {
                float y = ysh[(pbase + pp) * 64 + k];
                acc[0][pp] = fmaf(w0, y, acc[0][pp]);
                acc[1][pp] = fmaf(w1v, y, acc[1][pp]);
                acc[2][pp] = fmaf(w2v, y, acc[2][pp]);
                acc[3][pp] = fmaf(w3v, y, acc[3][pp]);
            }
        }
        #pragma unroll
        for (int pp = 0; pp < 2; pp++)
            #pragma unroll
            for (int cc = 0; cc < 4; cc++) {
                float h = acc[cc][pp] + b1[cbase + cc];
                hsh[(pbase + pp) * 64 + cbase + cc] = 0.5f * h * (1.f + erff(h * 0.70710678118654752f));
            }
    }
    __syncthreads();
    #pragma unroll
    for (int i = 0; i < 32; i++) {
        int lin = tid + i * 128;
        Wsh[(lin & 63) * 65 + (lin >> 6)] = w2[(lin >> 6) * 64 + (lin & 63)];
    }
    __syncthreads();
    {
        float acc[4][2] = {};
        #pragma unroll 4
        for (int k = 0; k < 64; k++) {
            float w0 = Wsh[k * 65 + cbase + 0];
            float w1v = Wsh[k * 65 + cbase + 1];
            float w2v = Wsh[k * 65 + cbase + 2];
            float w3v = Wsh[k * 65 + cbase + 3];
            #pragma unroll
            for (int pp = 0; pp < 2; pp++) {
                float y = hsh[(pbase + pp) * 64 + k];
                acc[0][pp] = fmaf(w0, y, acc[0][pp]);
                acc[1][pp] = fmaf(w1v, y, acc[1][pp]);
                acc[2][pp] = fmaf(w2v, y, acc[2][pp]);
                acc[3][pp] = fmaf(w3v, y, acc[3][pp]);
            }
        }
        #pragma unroll
        for (int pp = 0; pp < 2; pp++) {
            int lpix = pbase + pp;
            size_t base = ((size_t)b * NPIX + p0 + lpix) * CCH;
            #pragma unroll
            for (int cc = 0; cc < 4; cc++) {
                int c = cbase + cc;
                float val = acc[cc][pp] + b2[c] + tsh[lpix * 64 + c];
                if (c == 0) val = xprev[base];
                xout[base + c] = val;
            }
        }
    }
}

extern "C" void kernel_launch(void* const* d_in, const int* in_sizes, int n_in,
                              void* d_out, int out_size) {
    const float* x = (const float*)d_in[0];
    const void* masks = d_in[1];
    const float* p0_w = (const float*)d_in[2];
    const float* p0_b = (const float*)d_in[3];
    const float* p1_w = (const float*)d_in[4];
    const float* p1_b = (const float*)d_in[5];
    const float* fc0_w = (const float*)d_in[6];
    const float* fc0_b = (const float*)d_in[7];
    const float* fc1_w = (const float*)d_in[8];
    const float* n0w = (const float*)d_in[9];
    const float* n0b = (const float*)d_in[10];
    const float* ln1w = (const float*)d_in[11];
    const float* ln1b = (const float*)d_in[12];
    const float* qkvw = (const float*)d_in[13];
    const float* outw = (const float*)d_in[14];
    const float* outb = (const float*)d_in[15];
    const float* ln2w = (const float*)d_in[16];
    const float* ln2b = (const float*)d_in[17];
    const float* ff1w = (const float*)d_in[18];
    const float* ff1b = (const float*)d_in[19];
    const float* ff2w = (const float*)d_in[20];
    const float* ff2b = (const float*)d_in[21];
    float* out = (float*)d_out;

    cudaFuncSetAttribute(k_conv_mma, cudaFuncAttributeMaxDynamicSharedMemorySize, CONV_SMEM_BYTES);
    cudaFuncSetAttribute(k_fc1_mma, cudaFuncAttributeMaxDynamicSharedMemorySize, FC1_SMEM_BYTES);
    cudaFuncSetAttribute(k_qkv_mma, cudaFuncAttributeMaxDynamicSharedMemorySize, QKV_SMEM_BYTES);

    k_fold<<<288, 256>>>(fc0_w, fc0_b, p0_w, p0_b, p1_w, p1_b);
    k_prepw<<<48, 256>>>(qkvw, fc1_w);
    k_maskdetect<<<1, 1024>>>((const unsigned char*)masks, 6 * BATCH * NPIX);

    void* sym = nullptr;
    cudaGetSymbolAddress(&sym, g_xbuf);
    float* buf0 = (float*)sym;
    float* buf1 = buf0 + BATCH * NPIX * CCH;

    const float* cur = x;
    for (int s = 0; s < 6; s++) {
        float* stage = (s & 1) ? buf1 : buf0;
        float* nxt = (s == 5) ? out : stage;
        k_conv_mma<<<256, 256, CONV_SMEM_BYTES>>>(cur);
        k_fc1_mma<<<512, 256, FC1_SMEM_BYTES>>>(cur, n0w, n0b, masks, s, stage);
        k_qkv_mma<<<512, 256, QKV_SMEM_BYTES>>>(stage, ln1w, ln1b);
        k_attn<<<1024, 128>>>(stage, outw, outb);
        k_ff<<<2048, 128>>>(cur, ln2w, ln2b, ff1w, ff1b, ff2w, ff2b, nxt);
        cur = nxt;
    }
}

// round 9
// speedup vs baseline: 1.7465x; 1.1149x over previous
#include <cuda_runtime.h>
#include <math.h>
#include <stdint.h>

#define BATCH 8
#define NPIX 4096
#define CCH 64
#define HID 128
#define ATT_SCALE 0.25f

static __device__ float g_Wswz[9 * 128 * 64];    // pre-swizzled tf32 conv weights [tap][o][64]
static __device__ float g_QKVswz[192 * 64];      // pre-swizzled tf32 qkv weights [o][64]
static __device__ float g_FC1swz[64 * 128];      // pre-swizzled tf32 fc1 weights [o][128]
static __device__ float g_beff[HID];
static __device__ float g_xbuf[2][BATCH * NPIX * CCH];
static __device__ float g_hd[BATCH * NPIX * HID];
static __device__ float g_part[256 * 2];
static __device__ float g_q[BATCH * NPIX * CCH];
static __device__ float g_k[BATCH * NPIX * CCH];
static __device__ float g_v[BATCH * NPIX * CCH];
static __device__ int g_maskmode;

__device__ __forceinline__ uint32_t f2tf32(float f) {
    uint32_t u;
    asm("cvt.rna.tf32.f32 %0, %1;" : "=r"(u) : "f"(f));
    return u;
}

__device__ __forceinline__ int swz_pos(int c, int par) {
    int t4 = c & 3, idx = c >> 2;
    int pi = (t4 * 4 + (((idx >> 2) + t4) & 3)) ^ par;
    return pi * 4 + (idx & 3);
}

__global__ void k_maskdetect(const unsigned char* m, int nbytes) {
    __shared__ int hasBig, hasMis;
    if (threadIdx.x == 0) { hasBig = 0; hasMis = 0; }
    __syncthreads();
    for (int i = threadIdx.x; i < nbytes; i += blockDim.x) {
        unsigned char v = m[i];
        if (v > 1) hasBig = 1;
        else if (v && (i & 3)) hasMis = 1;
    }
    __syncthreads();
    if (threadIdx.x == 0) g_maskmode = (!hasBig && hasMis) ? 1 : 0;
}

__global__ void k_fold(const float* __restrict__ fc0_w, const float* __restrict__ fc0_b,
                       const float* __restrict__ p0_w, const float* __restrict__ p0_b,
                       const float* __restrict__ p1_w, const float* __restrict__ p1_b) {
    int t = blockIdx.x * 256 + threadIdx.x;
    if (t >= HID * 576) return;
    int o = t / 576, k = t - o * 576;
    int tap = k >> 6, c = k & 63;
    const float* f1 = fc0_w + o * 192 + 64;
    const float* f2 = fc0_w + o * 192 + 128;
    float acc = 0.f;
    for (int m = 0; m < 64; m++) {
        acc = fmaf(f1[m], p0_w[(m * 64 + c) * 9 + tap], acc);
        acc = fmaf(f2[m], p1_w[(m * 64 + c) * 9 + tap], acc);
    }
    if (tap == 4) acc += fc0_w[o * 192 + c];
    g_Wswz[(tap * 128 + o) * 64 + swz_pos(c, o & 1)] = __uint_as_float(f2tf32(acc));
    if (k == 0) {
        float b = fc0_b[o];
        for (int m = 0; m < 64; m++) {
            b = fmaf(f1[m], p0_b[m], b);
            b = fmaf(f2[m], p1_b[m], b);
        }
        g_beff[o] = b;
    }
}

__global__ void k_prepw(const float* __restrict__ qkvw, const float* __restrict__ fc1w) {
    int t = blockIdx.x * 256 + threadIdx.x;
    if (t < 192 * 64) {
        int o = t >> 6, k = t & 63;
        g_QKVswz[o * 64 + swz_pos(k, o & 1)] = __uint_as_float(f2tf32(qkvw[t]));
    }
    if (t < 64 * 128) {
        int o = t >> 7, k = t & 127;
        int half = k >> 6, kk = k & 63;
        g_FC1swz[o * 128 + half * 64 + swz_pos(kk, o & 1)] = __uint_as_float(f2tf32(fc1w[t]));
    }
}

__device__ __forceinline__ int refl(int v) { return v < 0 ? -v : (v > 63 ? 126 - v : v); }

__device__ __forceinline__ void mma_tf32(float* c, const uint32_t* a, uint32_t b0, uint32_t b1) {
    asm volatile(
        "mma.sync.aligned.m16n8k8.row.col.f32.tf32.tf32.f32 "
        "{%0,%1,%2,%3}, {%4,%5,%6,%7}, {%8,%9}, {%0,%1,%2,%3};"
        : "+f"(c[0]), "+f"(c[1]), "+f"(c[2]), "+f"(c[3])
        : "r"(a[0]), "r"(a[1]), "r"(a[2]), "r"(a[3]), "r"(b0), "r"(b1));
}

// ---------------- tensor-core conv: 128 pix x 128 out per block ----------------
#define XH_FLOATS (264 * 64)
#define W_FLOATS (128 * 64)
#define CONV_SMEM_BYTES ((XH_FLOATS + W_FLOATS) * 4)

__global__ void __launch_bounds__(256, 2) k_conv_mma(const float* __restrict__ xin) {
    extern __shared__ float sm[];
    float* Xh = sm;
    float* Wsh = sm + XH_FLOATS;
    int tid = threadIdx.x;
    int batch = blockIdx.x >> 5;
    int y0 = (blockIdx.x & 31) << 1;
    const float* xb = xin + (size_t)batch * NPIX * CCH;

    #pragma unroll 2
    for (int i = 0; i < 66; i++) {
        int lin = i * 256 + tid;
        int ch = lin & 63;
        int hp = lin >> 6;
        int hr = hp / 66, hc = hp - hr * 66;
        int gy = refl(y0 + hr - 1), gx = refl(hc - 1);
        float v = xb[(gy * 64 + gx) * CCH + ch];
        Xh[hp * 64 + swz_pos(ch, hp & 1)] = __uint_as_float(f2tf32(v));
    }

    int warp = tid >> 5, lane = tid & 31;
    int g = lane >> 2, t4 = lane & 3;
    int pixBase = (warp >> 1) * 32;
    int nBase = (warp & 1) * 64;

    float acc[2][8][4];
    #pragma unroll
    for (int m = 0; m < 2; m++)
        #pragma unroll
        for (int n = 0; n < 8; n++)
            #pragma unroll
            for (int j2 = 0; j2 < 4; j2++) acc[m][n][j2] = 0.f;

    for (int tap = 0; tap < 9; tap++) {
        int dy = tap / 3, dx = tap - dy * 3;
        __syncthreads();
        {
            const float4* wsrc = (const float4*)(g_Wswz + tap * (128 * 64));
            float4* wdst = (float4*)Wsh;
            #pragma unroll
            for (int i = 0; i < 8; i++) wdst[i * 256 + tid] = wsrc[i * 256 + tid];
        }
        __syncthreads();

        #pragma unroll
        for (int j = 0; j < 4; j++) {
            int pibase = t4 * 4 + ((j + t4) & 3);
            float4 av[4];
            #pragma unroll
            for (int r = 0; r < 4; r++) {
                int pr = pixBase + r * 8 + g;
                int hb = ((pr >> 6) + dy) * 66 + (pr & 63) + dx;
                av[r] = *(const float4*)&Xh[hb * 64 + ((pibase ^ (hb & 1)) << 2)];
            }
            uint32_t aH0m0[4] = {__float_as_uint(av[0].x), __float_as_uint(av[1].x),
                                 __float_as_uint(av[0].y), __float_as_uint(av[1].y)};
            uint32_t aH1m0[4] = {__float_as_uint(av[0].z), __float_as_uint(av[1].z),
                                 __float_as_uint(av[0].w), __float_as_uint(av[1].w)};
            uint32_t aH0m1[4] = {__float_as_uint(av[2].x), __float_as_uint(av[3].x),
                                 __float_as_uint(av[2].y), __float_as_uint(av[3].y)};
            uint32_t aH1m1[4] = {__float_as_uint(av[2].z), __float_as_uint(av[3].z),
                                 __float_as_uint(av[2].w), __float_as_uint(av[3].w)};
            #pragma unroll
            for (int n = 0; n < 8; n++) {
                int o = nBase + n * 8 + g;
                float4 bv = *(const float4*)&Wsh[o * 64 + ((pibase ^ (o & 1)) << 2)];
                uint32_t b0 = __float_as_uint(bv.x), b1 = __float_as_uint(bv.y);
                uint32_t b2 = __float_as_uint(bv.z), b3 = __float_as_uint(bv.w);
                mma_tf32(acc[0][n], aH0m0, b0, b1);
                mma_tf32(acc[0][n], aH1m0, b2, b3);
                mma_tf32(acc[1][n], aH0m1, b0, b1);
                mma_tf32(acc[1][n], aH1m1, b2, b3);
            }
        }
    }
    __syncthreads();

    float s = 0.f, sq = 0.f;
    #pragma unroll
    for (int m = 0; m < 2; m++) {
        int p_lo = pixBase + m * 16 + g;
        int p_hi = p_lo + 8;
        size_t row_lo = ((size_t)batch * NPIX + y0 * 64 + p_lo) * HID;
        size_t row_hi = ((size_t)batch * NPIX + y0 * 64 + p_hi) * HID;
        #pragma unroll
        for (int n = 0; n < 8; n++) {
            int col = nBase + n * 8 + 2 * t4;
            float bo0 = g_beff[col], bo1 = g_beff[col + 1];
            float r0 = fmaxf(acc[m][n][0] + bo0, 0.f);
            float r1 = fmaxf(acc[m][n][1] + bo1, 0.f);
            float r2 = fmaxf(acc[m][n][2] + bo0, 0.f);
            float r3 = fmaxf(acc[m][n][3] + bo1, 0.f);
            *(float2*)&g_hd[row_lo + col] = make_float2(r0, r1);
            *(float2*)&g_hd[row_hi + col] = make_float2(r2, r3);
            s += r0 + r1 + r2 + r3;
            sq += r0 * r0 + r1 * r1 + r2 * r2 + r3 * r3;
        }
    }
    float* red = sm;
    red[tid] = s; red[256 + tid] = sq;
    __syncthreads();
    for (int st = 128; st > 0; st >>= 1) {
        if (tid < st) { red[tid] += red[tid + st]; red[256 + tid] += red[256 + tid + st]; }
        __syncthreads();
    }
    if (tid == 0) { g_part[blockIdx.x * 2] = red[0]; g_part[blockIdx.x * 2 + 1] = red[256]; }
}

// ---------------- fused fc1 + qkv: 64 px per block ----------------
// smem: pool[16384] (fc1: ysh 8192 + Wsh 8192 / qkv: ysh2 4096 + WshQ 12288), xsh[4096]
#define FQ_SMEM_BYTES ((16384 + 4096) * 4)

__global__ void __launch_bounds__(256, 2) k_fc1qkv(const float* __restrict__ xin,
                                                   const float* __restrict__ nw,
                                                   const float* __restrict__ nb,
                                                   const void* __restrict__ mask, int s,
                                                   float* __restrict__ xout,
                                                   const float* __restrict__ lw,
                                                   const float* __restrict__ lb) {
    extern __shared__ float sm[];
    float* pool = sm;
    float* xsh = sm + 16384;          // [64][64] xn values
    __shared__ float s_mu, s_rs;
    int tid = threadIdx.x;
    int b = blockIdx.x >> 6;
    int p0 = (blockIdx.x & 63) << 6;
    int warp = tid >> 5, lane = tid & 31;
    int g = lane >> 2, t4 = lane & 3;

    // ===================== Part A: fc1 =====================
    float* ysh = pool;                // [64][128]
    float* Wsh = pool + 64 * 128;     // [64][128]

    if (tid < 32) {
        float ss = g_part[(b * 32 + tid) * 2];
        float sq = g_part[(b * 32 + tid) * 2 + 1];
        #pragma unroll
        for (int o = 16; o > 0; o >>= 1) {
            ss += __shfl_xor_sync(0xffffffffu, ss, o);
            sq += __shfl_xor_sync(0xffffffffu, sq, o);
        }
        if (tid == 0) {
            const float inv = 1.f / 524288.f;
            float mu = ss * inv;
            s_mu = mu;
            s_rs = rsqrtf(sq * inv - mu * mu + 1e-5f);
        }
    }
    {
        const float4* wsrc = (const float4*)g_FC1swz;
        float4* wdst = (float4*)Wsh;
        #pragma unroll
        for (int i = 0; i < 8; i++) wdst[i * 256 + tid] = wsrc[i * 256 + tid];
    }
    __syncthreads();
    float mu = s_mu, rs = s_rs;

    #pragma unroll
    for (int i = 0; i < 32; i++) {
        int lin = i * 256 + tid;
        int pix = lin >> 7, kk = lin & 127;
        size_t gi = ((size_t)b * NPIX + p0 + pix) * HID + kk;
        int ii = (p0 + pix) * HID + kk;
        float y = (g_hd[gi] - mu) * rs * nw[ii] + nb[ii];
        int half = kk >> 6, kc = kk & 63;
        ysh[pix * 128 + half * 64 + swz_pos(kc, pix & 1)] = __uint_as_float(f2tf32(y));
    }
    __syncthreads();

    {
        int pixBase = (warp & 1) * 32;
        int oBase = (warp >> 1) * 16;

        float acc[2][2][4];
        #pragma unroll
        for (int m = 0; m < 2; m++)
            #pragma unroll
            for (int n = 0; n < 2; n++)
                #pragma unroll
                for (int j = 0; j < 4; j++) acc[m][n][j] = 0.f;

        #pragma unroll
        for (int half = 0; half < 2; half++) {
            #pragma unroll
            for (int j = 0; j < 4; j++) {
                int pibase = t4 * 4 + ((j + t4) & 3);
                float4 av[4];
                #pragma unroll
                for (int r = 0; r < 4; r++) {
                    int pr = pixBase + r * 8 + g;
                    av[r] = *(const float4*)&ysh[pr * 128 + half * 64 + ((pibase ^ (pr & 1)) << 2)];
                }
                uint32_t aH0m0[4] = {__float_as_uint(av[0].x), __float_as_uint(av[1].x),
                                     __float_as_uint(av[0].y), __float_as_uint(av[1].y)};
                uint32_t aH1m0[4] = {__float_as_uint(av[0].z), __float_as_uint(av[1].z),
                                     __float_as_uint(av[0].w), __float_as_uint(av[1].w)};
                uint32_t aH0m1[4] = {__float_as_uint(av[2].x), __float_as_uint(av[3].x),
                                     __float_as_uint(av[2].y), __float_as_uint(av[3].y)};
                uint32_t aH1m1[4] = {__float_as_uint(av[2].z), __float_as_uint(av[3].z),
                                     __float_as_uint(av[2].w), __float_as_uint(av[3].w)};
                #pragma unroll
                for (int n = 0; n < 2; n++) {
                    int o = oBase + n * 8 + g;
                    float4 bv = *(const float4*)&Wsh[o * 128 + half * 64 + ((pibase ^ (o & 1)) << 2)];
                    uint32_t b0 = __float_as_uint(bv.x), b1 = __float_as_uint(bv.y);
                    uint32_t b2 = __float_as_uint(bv.z), b3 = __float_as_uint(bv.w);
                    mma_tf32(acc[0][n], aH0m0, b0, b1);
                    mma_tf32(acc[0][n], aH1m0, b2, b3);
                    mma_tf32(acc[1][n], aH0m1, b0, b1);
                    mma_tf32(acc[1][n], aH1m1, b2, b3);
                }
            }
        }

        int mode = g_maskmode;
        #pragma unroll
        for (int m = 0; m < 2; m++) {
            int p_lo = pixBase + m * 16 + g;
            int p_hi = p_lo + 8;
            size_t gplo = (size_t)b * NPIX + p0 + p_lo;
            size_t gphi = (size_t)b * NPIX + p0 + p_hi;
            size_t milo = (size_t)s * 32768 + gplo;
            size_t mihi = (size_t)s * 32768 + gphi;
            float mvlo, mvhi;
            if (mode) {
                mvlo = ((const unsigned char*)mask)[milo] ? 1.f : 0.f;
                mvhi = ((const unsigned char*)mask)[mihi] ? 1.f : 0.f;
            } else {
                mvlo = ((const unsigned int*)mask)[milo] ? 1.f : 0.f;
                mvhi = ((const unsigned int*)mask)[mihi] ? 1.f : 0.f;
            }
            #pragma unroll
            for (int n = 0; n < 2; n++) {
                int col = oBase + n * 8 + 2 * t4;
                float2 x0 = *(const float2*)&xin[gplo * CCH + col];
                float2 x1 = *(const float2*)&xin[gphi * CCH + col];
                float2 o0 = make_float2(x0.x + acc[m][n][0] * mvlo, x0.y + acc[m][n][1] * mvlo);
                float2 o1 = make_float2(x1.x + acc[m][n][2] * mvhi, x1.y + acc[m][n][3] * mvhi);
                *(float2*)&xout[gplo * CCH + col] = o0;
                *(float2*)&xout[gphi * CCH + col] = o1;
                *(float2*)&xsh[p_lo * 64 + col] = o0;
                *(float2*)&xsh[p_hi * 64 + col] = o1;
            }
        }
    }
    __syncthreads();

    // ===================== Part B: LN + qkv =====================
    float* ysh2 = pool;               // [64][64] swizzled
    float* WshQ = pool + 64 * 64;     // [192][64] swizzled

    #pragma unroll
    for (int k = 0; k < 8; k++) {
        int pix = warp * 8 + k;
        float v0 = xsh[pix * 64 + lane], v1 = xsh[pix * 64 + lane + 32];
        float ss = v0 + v1, sq = v0 * v0 + v1 * v1;
        #pragma unroll
        for (int o = 16; o > 0; o >>= 1) {
            ss += __shfl_xor_sync(0xffffffffu, ss, o);
            sq += __shfl_xor_sync(0xffffffffu, sq, o);
        }
        float mu2 = ss * (1.f / 64.f);
        float rsg = rsqrtf(sq * (1.f / 64.f) - mu2 * mu2 + 1e-5f);
        float y0 = (v0 - mu2) * rsg * lw[lane] + lb[lane];
        float y1 = (v1 - mu2) * rsg * lw[lane + 32] + lb[lane + 32];
        ysh2[pix * 64 + swz_pos(lane, pix & 1)] = __uint_as_float(f2tf32(y0));
        ysh2[pix * 64 + swz_pos(lane + 32, pix & 1)] = __uint_as_float(f2tf32(y1));
    }
    {
        const float4* wsrc = (const float4*)g_QKVswz;
        float4* wdst = (float4*)WshQ;
        #pragma unroll
        for (int i = 0; i < 12; i++) wdst[i * 256 + tid] = wsrc[i * 256 + tid];
    }
    __syncthreads();

    {
        int pixBase = (warp & 1) * 32;
        int oBase = (warp >> 1) * 48;

        float acc[2][6][4];
        #pragma unroll
        for (int m = 0; m < 2; m++)
            #pragma unroll
            for (int n = 0; n < 6; n++)
                #pragma unroll
                for (int j = 0; j < 4; j++) acc[m][n][j] = 0.f;

        #pragma unroll
        for (int j = 0; j < 4; j++) {
            int pibase = t4 * 4 + ((j + t4) & 3);
            float4 av[4];
            #pragma unroll
            for (int r = 0; r < 4; r++) {
                int pr = pixBase + r * 8 + g;
                av[r] = *(const float4*)&ysh2[pr * 64 + ((pibase ^ (pr & 1)) << 2)];
            }
            uint32_t aH0m0[4] = {__float_as_uint(av[0].x), __float_as_uint(av[1].x),
                                 __float_as_uint(av[0].y), __float_as_uint(av[1].y)};
            uint32_t aH1m0[4] = {__float_as_uint(av[0].z), __float_as_uint(av[1].z),
                                 __float_as_uint(av[0].w), __float_as_uint(av[1].w)};
            uint32_t aH0m1[4] = {__float_as_uint(av[2].x), __float_as_uint(av[3].x),
                                 __float_as_uint(av[2].y), __float_as_uint(av[3].y)};
            uint32_t aH1m1[4] = {__float_as_uint(av[2].z), __float_as_uint(av[3].z),
                                 __float_as_uint(av[2].w), __float_as_uint(av[3].w)};
            #pragma unroll
            for (int n = 0; n < 6; n++) {
                int o = oBase + n * 8 + g;
                float4 bv = *(const float4*)&WshQ[o * 64 + ((pibase ^ (o & 1)) << 2)];
                uint32_t b0 = __float_as_uint(bv.x), b1 = __float_as_uint(bv.y);
                uint32_t b2 = __float_as_uint(bv.z), b3 = __float_as_uint(bv.w);
                mma_tf32(acc[0][n], aH0m0, b0, b1);
                mma_tf32(acc[0][n], aH1m0, b2, b3);
                mma_tf32(acc[1][n], aH0m1, b0, b1);
                mma_tf32(acc[1][n], aH1m1, b2, b3);
            }
        }

        #pragma unroll
        for (int m = 0; m < 2; m++) {
            int p_lo = pixBase + m * 16 + g;
            int p_hi = p_lo + 8;
            size_t gplo = (size_t)b * NPIX + p0 + p_lo;
            size_t gphi = (size_t)b * NPIX + p0 + p_hi;
            #pragma unroll
            for (int n = 0; n < 6; n++) {
                int col = oBase + n * 8 + 2 * t4;
                int region = col >> 6;
                int c = col & 63;
                float* dst = (region == 0) ? g_q : (region == 1) ? g_k : g_v;
                *(float2*)&dst[gplo * CCH + c] = make_float2(acc[m][n][0], acc[m][n][1]);
                *(float2*)&dst[gphi * CCH + c] = make_float2(acc[m][n][2], acc[m][n][3]);
            }
        }
    }
}

// ---------------- fused attn + out-proj + ff: 32 px per block ----------------
// smem floats: kv[7808] (ksh/vsh, later wsh) + osh[2080] + tsh[2080] + ysh[2080] + hsh[2080]
#define AF_SMEM_BYTES ((7808 + 2080 * 4) * 4)

__global__ void __launch_bounds__(128) k_attn_ff(const float* __restrict__ xn,
                                                 const float* __restrict__ xprev,
                                                 const float* __restrict__ outw,
                                                 const float* __restrict__ outb,
                                                 const float* __restrict__ lw2,
                                                 const float* __restrict__ lb2,
                                                 const float* __restrict__ w1,
                                                 const float* __restrict__ b1,
                                                 const float* __restrict__ w2,
                                                 const float* __restrict__ b2,
                                                 float* __restrict__ xout) {
    extern __shared__ float sm[];
    float* ksh = sm;                  // [64ch][61pos]
    float* vsh = sm + 3904;
    float* wsh = sm;                  // overlays kv region after attention
    float* osh = sm + 7808;           // [32][65]
    float* tsh = osh + 2080;          // [32][65]
    float* ysh = tsh + 2080;          // [32][65]
    float* hsh = ysh + 2080;          // [32][65]
    int tid = threadIdx.x;
    int b = blockIdx.x >> 7;
    int tile = blockIdx.x & 127;
    int tx0 = (tile & 7) << 3;
    int ty0 = (tile >> 3) << 2;

    // phase 0: k/v halo
    #pragma unroll
    for (int i = 0; i < 30; i++) {
        int lin = tid + i * 128;
        int pos = lin >> 6, ch = lin & 63;
        int hy = pos / 10, hx = pos - hy * 10;
        int gy = ty0 + hy - 1, gx = tx0 + hx - 1;
        float kv = 0.f, vv = 0.f;
        if ((unsigned)gy < 64u && (unsigned)gx < 64u) {
            size_t a = ((size_t)b * NPIX + gy * 64 + gx) * CCH + ch;
            kv = g_k[a]; vv = g_v[a];
        }
        ksh[ch * 61 + pos] = kv;
        vsh[ch * 61 + pos] = vv;
    }
    __syncthreads();

    // phase 1: attention (warp = head, lane = pixel)
    {
        int head = tid >> 5, lp = tid & 31;
        int py = lp >> 3, px = lp & 7;
        int gy = ty0 + py, gx = tx0 + px;
        size_t qbase = ((size_t)b * NPIX + gy * 64 + gx) * CCH + head * 16;
        float q[16];
        #pragma unroll
        for (int i = 0; i < 4; i++) {
            float4 t4v = *(const float4*)&g_q[qbase + i * 4];
            q[i * 4] = t4v.x; q[i * 4 + 1] = t4v.y; q[i * 4 + 2] = t4v.z; q[i * 4 + 3] = t4v.w;
        }
        float lg[9];
        #pragma unroll
        for (int t = 0; t < 9; t++) {
            int pos = (py + t / 3) * 10 + px + t % 3;
            float d = 0.f;
            #pragma unroll
            for (int i = 0; i < 16; i++) d = fmaf(q[i], ksh[(head * 16 + i) * 61 + pos], d);
            lg[t] = d * ATT_SCALE;
        }
        float m = lg[0];
        #pragma unroll
        for (int t = 1; t < 9; t++) m = fmaxf(m, lg[t]);
        float e[9], ssum = 0.f;
        #pragma unroll
        for (int t = 0; t < 9; t++) { e[t] = __expf(lg[t] - m); ssum += e[t]; }
        float inv = 1.f / ssum;
        float o[16] = {};
        #pragma unroll
        for (int t = 0; t < 9; t++) {
            int pos = (py + t / 3) * 10 + px + t % 3;
            float a = e[t] * inv;
            #pragma unroll
            for (int i = 0; i < 16; i++) o[i] = fmaf(a, vsh[(head * 16 + i) * 61 + pos], o[i]);
        }
        #pragma unroll
        for (int i = 0; i < 16; i++) osh[lp * 65 + head * 16 + i] = o[i];
    }
    __syncthreads();

    // phase 2: stage out-proj weights (overlay kv region)
    #pragma unroll
    for (int i = 0; i < 32; i++) {
        int lin = tid + i * 128;
        wsh[(lin & 63) * 65 + (lin >> 6)] = outw[(lin >> 6) * 64 + (lin & 63)];
    }
    __syncthreads();

    int cg = tid & 15, pg = tid >> 4;
    int cbase = cg * 4, pbase = pg * 4;

    // phase 3: out projection + residual -> tsh
    {
        float acc[4][4] = {};
        #pragma unroll 4
        for (int k = 0; k < 64; k++) {
            float w0 = wsh[k * 65 + cbase + 0];
            float w1v = wsh[k * 65 + cbase + 1];
            float w2v = wsh[k * 65 + cbase + 2];
            float w3v = wsh[k * 65 + cbase + 3];
            #pragma unroll
            for (int pp = 0; pp < 4; pp++) {
                float ov = osh[(pbase + pp) * 65 + k];
                acc[0][pp] = fmaf(w0, ov, acc[0][pp]);
                acc[1][pp] = fmaf(w1v, ov, acc[1][pp]);
                acc[2][pp] = fmaf(w2v, ov, acc[2][pp]);
                acc[3][pp] = fmaf(w3v, ov, acc[3][pp]);
            }
        }
        #pragma unroll
        for (int pp = 0; pp < 4; pp++) {
            int lp2 = pbase + pp;
            int gp = (ty0 + (lp2 >> 3)) * 64 + tx0 + (lp2 & 7);
            size_t base = ((size_t)b * NPIX + gp) * CCH;
            #pragma unroll
            for (int cc = 0; cc < 4; cc++) {
                int c = cbase + cc;
                tsh[lp2 * 65 + c] = acc[cc][pp] + outb[c] + xn[base + c];
            }
        }
    }
    __syncthreads();

    // phase 4: LN2 per pixel (warp handles 8 px) + stage w1 (overlay wsh)
    {
        int warp = tid >> 5, lane = tid & 31;
        #pragma unroll
        for (int k = 0; k < 8; k++) {
            int pix = warp * 8 + k;
            float v0 = tsh[pix * 65 + lane], v1 = tsh[pix * 65 + lane + 32];
            float ss = v0 + v1, sq = v0 * v0 + v1 * v1;
            #pragma unroll
            for (int o = 16; o > 0; o >>= 1) {
                ss += __shfl_xor_sync(0xffffffffu, ss, o);
                sq += __shfl_xor_sync(0xffffffffu, sq, o);
            }
            float mu = ss * (1.f / 64.f);
            float rsg = rsqrtf(sq * (1.f / 64.f) - mu * mu + 1e-5f);
            ysh[pix * 65 + lane] = (v0 - mu) * rsg * lw2[lane] + lb2[lane];
            ysh[pix * 65 + lane + 32] = (v1 - mu) * rsg * lw2[lane + 32] + lb2[lane + 32];
        }
    }
    #pragma unroll
    for (int i = 0; i < 32; i++) {
        int lin = tid + i * 128;
        wsh[(lin & 63) * 65 + (lin >> 6)] = w1[(lin >> 6) * 64 + (lin & 63)];
    }
    __syncthreads();

    // phase 5: ff1 + GELU -> hsh
    {
        float acc[4][4] = {};
        #pragma unroll 4
        for (int k = 0; k < 64; k++) {
            float w0 = wsh[k * 65 + cbase + 0];
            float w1v = wsh[k * 65 + cbase + 1];
            float w2v = wsh[k * 65 + cbase + 2];
            float w3v = wsh[k * 65 + cbase + 3];
            #pragma unroll
            for (int pp = 0; pp < 4; pp++) {
                float y = ysh[(pbase + pp) * 65 + k];
                acc[0][pp] = fmaf(w0, y, acc[0][pp]);
                acc[1][pp] = fmaf(w1v, y, acc[1][pp]);
                acc[2][pp] = fmaf(w2v, y, acc[2][pp]);
                acc[3][pp] = fmaf(w3v, y, acc[3][pp]);
            }
        }
        #pragma unroll
        for (int pp = 0; pp < 4; pp++)
            #pragma unroll
            for (int cc = 0; cc < 4; cc++) {
                float h = acc[cc][pp] + b1[cbase + cc];
                hsh[(pbase + pp) * 65 + cbase + cc] =
                    0.5f * h * (1.f + erff(h * 0.70710678118654752f));
            }
    }
    __syncthreads();

    // stage w2
    #pragma unroll
    for (int i = 0; i < 32; i++) {
        int lin = tid + i * 128;
        wsh[(lin & 63) * 65 + (lin >> 6)] = w2[(lin >> 6) * 64 + (lin & 63)];
    }
    __syncthreads();

    // phase 6: ff2 + residual + ch0 restore -> global
    {
        float acc[4][4] = {};
        #pragma unroll 4
        for (int k = 0; k < 64; k++) {
            float w0 = wsh[k * 65 + cbase + 0];
            float w1v = wsh[k * 65 + cbase + 1];
            float w2v = wsh[k * 65 + cbase + 2];
            float w3v = wsh[k * 65 + cbase + 3];
            #pragma unroll
            for (int pp = 0; pp < 4; pp++) {
                float hv = hsh[(pbase + pp) * 65 + k];
                acc[0][pp] = fmaf(w0, hv, acc[0][pp]);
                acc[1][pp] = fmaf(w1v, hv, acc[1][pp]);
                acc[2][pp] = fmaf(w2v, hv, acc[2][pp]);
                acc[3][pp] = fmaf(w3v, hv, acc[3][pp]);
            }
        }
        #pragma unroll
        for (int pp = 0; pp < 4; pp++) {
            int lp2 = pbase + pp;
            int gp = (ty0 + (lp2 >> 3)) * 64 + tx0 + (lp2 & 7);
            size_t base = ((size_t)b * NPIX + gp) * CCH;
            #pragma unroll
            for (int cc = 0; cc < 4; cc++) {
                int c = cbase + cc;
                float val = acc[cc][pp] + b2[c] + tsh[lp2 * 65 + c];
                if (c == 0) val = xprev[base];
                xout[base + c] = val;
            }
        }
    }
}

extern "C" void kernel_launch(void* const* d_in, const int* in_sizes, int n_in,
                              void* d_out, int out_size) {
    const float* x = (const float*)d_in[0];
    const void* masks = d_in[1];
    const float* p0_w = (const float*)d_in[2];
    const float* p0_b = (const float*)d_in[3];
    const float* p1_w = (const float*)d_in[4];
    const float* p1_b = (const float*)d_in[5];
    const float* fc0_w = (const float*)d_in[6];
    const float* fc0_b = (const float*)d_in[7];
    const float* fc1_w = (const float*)d_in[8];
    const float* n0w = (const float*)d_in[9];
    const float* n0b = (const float*)d_in[10];
    const float* ln1w = (const float*)d_in[11];
    const float* ln1b = (const float*)d_in[12];
    const float* qkvw = (const float*)d_in[13];
    const float* outw = (const float*)d_in[14];
    const float* outb = (const float*)d_in[15];
    const float* ln2w = (const float*)d_in[16];
    const float* ln2b = (const float*)d_in[17];
    const float* ff1w = (const float*)d_in[18];
    const float* ff1b = (const float*)d_in[19];
    const float* ff2w = (const float*)d_in[20];
    const float* ff2b = (const float*)d_in[21];
    float* out = (float*)d_out;

    cudaFuncSetAttribute(k_conv_mma, cudaFuncAttributeMaxDynamicSharedMemorySize, CONV_SMEM_BYTES);
    cudaFuncSetAttribute(k_fc1qkv, cudaFuncAttributeMaxDynamicSharedMemorySize, FQ_SMEM_BYTES);
    cudaFuncSetAttribute(k_attn_ff, cudaFuncAttributeMaxDynamicSharedMemorySize, AF_SMEM_BYTES);

    k_fold<<<288, 256>>>(fc0_w, fc0_b, p0_w, p0_b, p1_w, p1_b);
    k_prepw<<<48, 256>>>(qkvw, fc1_w);
    k_maskdetect<<<1, 1024>>>((const unsigned char*)masks, 6 * BATCH * NPIX);

    void* sym = nullptr;
    cudaGetSymbolAddress(&sym, g_xbuf);
    float* buf0 = (float*)sym;
    float* buf1 = buf0 + BATCH * NPIX * CCH;

    const float* cur = x;
    for (int s = 0; s < 6; s++) {
        float* stage = (s & 1) ? buf1 : buf0;
        float* nxt = (s == 5) ? out : stage;
        k_conv_mma<<<256, 256, CONV_SMEM_BYTES>>>(cur);
        k_fc1qkv<<<512, 256, FQ_SMEM_BYTES>>>(cur, n0w, n0b, masks, s, stage, ln1w, ln1b);
        k_attn_ff<<<1024, 128, AF_SMEM_BYTES>>>(stage, cur, outw, outb, ln2w, ln2b,
                                                ff1w, ff1b, ff2w, ff2b, nxt);
        cur = nxt;
    }
}

// round 10
// speedup vs baseline: 1.8578x; 1.0637x over previous
#include <cuda_runtime.h>
#include <math.h>
#include <stdint.h>

#define BATCH 8
#define NPIX 4096
#define CCH 64
#define HID 128
#define ATT_SCALE 0.25f

static __device__ float g_Wswz[9 * 128 * 64];    // pre-swizzled tf32 conv weights [tap][o][64]
static __device__ float g_QKVswz[192 * 64];      // pre-swizzled tf32 qkv weights [o][64]
static __device__ float g_FC1swz[64 * 128];      // pre-swizzled tf32 fc1 weights [o][128]
static __device__ float g_OUTp[64 * 66];         // pair-interleaved tf32 out-proj weights
static __device__ float g_FF1p[64 * 66];
static __device__ float g_FF2p[64 * 66];
static __device__ float g_beff[HID];
static __device__ float g_xbuf[2][BATCH * NPIX * CCH];
static __device__ float g_hd[BATCH * NPIX * HID];
static __device__ float g_part[256 * 2];
static __device__ float g_q[BATCH * NPIX * CCH];
static __device__ float g_k[BATCH * NPIX * CCH];
static __device__ float g_v[BATCH * NPIX * CCH];
static __device__ int g_maskmode;

__device__ __forceinline__ uint32_t f2tf32(float f) {
    uint32_t u;
    asm("cvt.rna.tf32.f32 %0, %1;" : "=r"(u) : "f"(f));
    return u;
}

__device__ __forceinline__ int swz_pos(int c, int par) {
    int t4 = c & 3, idx = c >> 2;
    int pi = (t4 * 4 + (((idx >> 2) + t4) & 3)) ^ par;
    return pi * 4 + (idx & 3);
}

// pair-interleaved position: (k, k+4) become adjacent within each 8-group
__device__ __forceinline__ int pairpos(int k) {
    return (k & 56) + ((k & 3) << 1) + ((k >> 2) & 1);
}

__global__ void k_maskdetect(const unsigned char* m, int nbytes) {
    __shared__ int hasBig, hasMis;
    if (threadIdx.x == 0) { hasBig = 0; hasMis = 0; }
    __syncthreads();
    for (int i = threadIdx.x; i < nbytes; i += blockDim.x) {
        unsigned char v = m[i];
        if (v > 1) hasBig = 1;
        else if (v && (i & 3)) hasMis = 1;
    }
    __syncthreads();
    if (threadIdx.x == 0) g_maskmode = (!hasBig && hasMis) ? 1 : 0;
}

__global__ void k_fold(const float* __restrict__ fc0_w, const float* __restrict__ fc0_b,
                       const float* __restrict__ p0_w, const float* __restrict__ p0_b,
                       const float* __restrict__ p1_w, const float* __restrict__ p1_b) {
    int t = blockIdx.x * 256 + threadIdx.x;
    if (t >= HID * 576) return;
    int o = t / 576, k = t - o * 576;
    int tap = k >> 6, c = k & 63;
    const float* f1 = fc0_w + o * 192 + 64;
    const float* f2 = fc0_w + o * 192 + 128;
    float acc = 0.f;
    for (int m = 0; m < 64; m++) {
        acc = fmaf(f1[m], p0_w[(m * 64 + c) * 9 + tap], acc);
        acc = fmaf(f2[m], p1_w[(m * 64 + c) * 9 + tap], acc);
    }
    if (tap == 4) acc += fc0_w[o * 192 + c];
    g_Wswz[(tap * 128 + o) * 64 + swz_pos(c, o & 1)] = __uint_as_float(f2tf32(acc));
    if (k == 0) {
        float b = fc0_b[o];
        for (int m = 0; m < 64; m++) {
            b = fmaf(f1[m], p0_b[m], b);
            b = fmaf(f2[m], p1_b[m], b);
        }
        g_beff[o] = b;
    }
}

__global__ void k_prepw(const float* __restrict__ qkvw, const float* __restrict__ fc1w,
                        const float* __restrict__ outw, const float* __restrict__ ff1w,
                        const float* __restrict__ ff2w) {
    int t = blockIdx.x * 256 + threadIdx.x;
    if (t < 192 * 64) {
        int o = t >> 6, k = t & 63;
        g_QKVswz[o * 64 + swz_pos(k, o & 1)] = __uint_as_float(f2tf32(qkvw[t]));
    }
    if (t < 64 * 128) {
        int o = t >> 7, k = t & 127;
        int half = k >> 6, kk = k & 63;
        g_FC1swz[o * 128 + half * 64 + swz_pos(kk, o & 1)] = __uint_as_float(f2tf32(fc1w[t]));
    }
    if (t < 64 * 64) {
        int c = t >> 6, k = t & 63;
        int p = c * 66 + pairpos(k);
        g_OUTp[p] = __uint_as_float(f2tf32(outw[t]));
        g_FF1p[p] = __uint_as_float(f2tf32(ff1w[t]));
        g_FF2p[p] = __uint_as_float(f2tf32(ff2w[t]));
    }
    if (t < 128) {   // zero pad columns 64,65
        int c = t >> 1, pos = 64 + (t & 1);
        g_OUTp[c * 66 + pos] = 0.f;
        g_FF1p[c * 66 + pos] = 0.f;
        g_FF2p[c * 66 + pos] = 0.f;
    }
}

__device__ __forceinline__ int refl(int v) { return v < 0 ? -v : (v > 63 ? 126 - v : v); }

__device__ __forceinline__ void mma_tf32(float* c, const uint32_t* a, uint32_t b0, uint32_t b1) {
    asm volatile(
        "mma.sync.aligned.m16n8k8.row.col.f32.tf32.tf32.f32 "
        "{%0,%1,%2,%3}, {%4,%5,%6,%7}, {%8,%9}, {%0,%1,%2,%3};"
        : "+f"(c[0]), "+f"(c[1]), "+f"(c[2]), "+f"(c[3])
        : "r"(a[0]), "r"(a[1]), "r"(a[2]), "r"(a[3]), "r"(b0), "r"(b1));
}

// 32px x 64out x K64 GEMM on pair-interleaved stride-66 operands.
// warp layout: mw = warp&1 (16-px half), nw = warp>>1 (32-out half)
__device__ __forceinline__ void gemm32_66(const float* __restrict__ Ap,
                                          const float* __restrict__ Wp,
                                          int mw, int nw, int g, int t4,
                                          float acc[4][4]) {
    #pragma unroll
    for (int k0 = 0; k0 < 8; k0++) {
        int kb = k0 * 8 + 2 * t4;
        float2 a0 = *(const float2*)&Ap[(mw * 16 + g) * 66 + kb];
        float2 a1 = *(const float2*)&Ap[(mw * 16 + g + 8) * 66 + kb];
        uint32_t a[4] = {__float_as_uint(a0.x), __float_as_uint(a1.x),
                         __float_as_uint(a0.y), __float_as_uint(a1.y)};
        #pragma unroll
        for (int n = 0; n < 4; n++) {
            float2 b = *(const float2*)&Wp[(nw * 32 + n * 8 + g) * 66 + kb];
            mma_tf32(acc[n], a, __float_as_uint(b.x), __float_as_uint(b.y));
        }
    }
}

// ---------------- tensor-core conv: 128 pix x 128 out per block ----------------
#define XH_FLOATS (264 * 64)
#define W_FLOATS (128 * 64)
#define CONV_SMEM_BYTES ((XH_FLOATS + W_FLOATS) * 4)

__global__ void __launch_bounds__(256, 2) k_conv_mma(const float* __restrict__ xin) {
    extern __shared__ float sm[];
    float* Xh = sm;
    float* Wsh = sm + XH_FLOATS;
    int tid = threadIdx.x;
    int batch = blockIdx.x >> 5;
    int y0 = (blockIdx.x & 31) << 1;
    const float* xb = xin + (size_t)batch * NPIX * CCH;

    #pragma unroll 2
    for (int i = 0; i < 66; i++) {
        int lin = i * 256 + tid;
        int ch = lin & 63;
        int hp = lin >> 6;
        int hr = hp / 66, hc = hp - hr * 66;
        int gy = refl(y0 + hr - 1), gx = refl(hc - 1);
        float v = xb[(gy * 64 + gx) * CCH + ch];
        Xh[hp * 64 + swz_pos(ch, hp & 1)] = __uint_as_float(f2tf32(v));
    }

    int warp = tid >> 5, lane = tid & 31;
    int g = lane >> 2, t4 = lane & 3;
    int pixBase = (warp >> 1) * 32;
    int nBase = (warp & 1) * 64;

    float acc[2][8][4];
    #pragma unroll
    for (int m = 0; m < 2; m++)
        #pragma unroll
        for (int n = 0; n < 8; n++)
            #pragma unroll
            for (int j2 = 0; j2 < 4; j2++) acc[m][n][j2] = 0.f;

    for (int tap = 0; tap < 9; tap++) {
        int dy = tap / 3, dx = tap - dy * 3;
        __syncthreads();
        {
            const float4* wsrc = (const float4*)(g_Wswz + tap * (128 * 64));
            float4* wdst = (float4*)Wsh;
            #pragma unroll
            for (int i = 0; i < 8; i++) wdst[i * 256 + tid] = wsrc[i * 256 + tid];
        }
        __syncthreads();

        #pragma unroll
        for (int j = 0; j < 4; j++) {
            int pibase = t4 * 4 + ((j + t4) & 3);
            float4 av[4];
            #pragma unroll
            for (int r = 0; r < 4; r++) {
                int pr = pixBase + r * 8 + g;
                int hb = ((pr >> 6) + dy) * 66 + (pr & 63) + dx;
                av[r] = *(const float4*)&Xh[hb * 64 + ((pibase ^ (hb & 1)) << 2)];
            }
            uint32_t aH0m0[4] = {__float_as_uint(av[0].x), __float_as_uint(av[1].x),
                                 __float_as_uint(av[0].y), __float_as_uint(av[1].y)};
            uint32_t aH1m0[4] = {__float_as_uint(av[0].z), __float_as_uint(av[1].z),
                                 __float_as_uint(av[0].w), __float_as_uint(av[1].w)};
            uint32_t aH0m1[4] = {__float_as_uint(av[2].x), __float_as_uint(av[3].x),
                                 __float_as_uint(av[2].y), __float_as_uint(av[3].y)};
            uint32_t aH1m1[4] = {__float_as_uint(av[2].z), __float_as_uint(av[3].z),
                                 __float_as_uint(av[2].w), __float_as_uint(av[3].w)};
            #pragma unroll
            for (int n = 0; n < 8; n++) {
                int o = nBase + n * 8 + g;
                float4 bv = *(const float4*)&Wsh[o * 64 + ((pibase ^ (o & 1)) << 2)];
                uint32_t b0 = __float_as_uint(bv.x), b1 = __float_as_uint(bv.y);
                uint32_t b2 = __float_as_uint(bv.z), b3 = __float_as_uint(bv.w);
                mma_tf32(acc[0][n], aH0m0, b0, b1);
                mma_tf32(acc[0][n], aH1m0, b2, b3);
                mma_tf32(acc[1][n], aH0m1, b0, b1);
                mma_tf32(acc[1][n], aH1m1, b2, b3);
            }
        }
    }
    __syncthreads();

    float s = 0.f, sq = 0.f;
    #pragma unroll
    for (int m = 0; m < 2; m++) {
        int p_lo = pixBase + m * 16 + g;
        int p_hi = p_lo + 8;
        size_t row_lo = ((size_t)batch * NPIX + y0 * 64 + p_lo) * HID;
        size_t row_hi = ((size_t)batch * NPIX + y0 * 64 + p_hi) * HID;
        #pragma unroll
        for (int n = 0; n < 8; n++) {
            int col = nBase + n * 8 + 2 * t4;
            float bo0 = g_beff[col], bo1 = g_beff[col + 1];
            float r0 = fmaxf(acc[m][n][0] + bo0, 0.f);
            float r1 = fmaxf(acc[m][n][1] + bo1, 0.f);
            float r2 = fmaxf(acc[m][n][2] + bo0, 0.f);
            float r3 = fmaxf(acc[m][n][3] + bo1, 0.f);
            *(float2*)&g_hd[row_lo + col] = make_float2(r0, r1);
            *(float2*)&g_hd[row_hi + col] = make_float2(r2, r3);
            s += r0 + r1 + r2 + r3;
            sq += r0 * r0 + r1 * r1 + r2 * r2 + r3 * r3;
        }
    }
    float* red = sm;
    red[tid] = s; red[256 + tid] = sq;
    __syncthreads();
    for (int st = 128; st > 0; st >>= 1) {
        if (tid < st) { red[tid] += red[tid + st]; red[256 + tid] += red[256 + tid + st]; }
        __syncthreads();
    }
    if (tid == 0) { g_part[blockIdx.x * 2] = red[0]; g_part[blockIdx.x * 2 + 1] = red[256]; }
}

// ---------------- fused fc1 + qkv: 64 px per block ----------------
#define FQ_SMEM_BYTES ((16384 + 4096) * 4)

__global__ void __launch_bounds__(256, 2) k_fc1qkv(const float* __restrict__ xin,
                                                   const float* __restrict__ nw,
                                                   const float* __restrict__ nb,
                                                   const void* __restrict__ mask, int s,
                                                   float* __restrict__ xout,
                                                   const float* __restrict__ lw,
                                                   const float* __restrict__ lb) {
    extern __shared__ float sm[];
    float* pool = sm;
    float* xsh = sm + 16384;
    __shared__ float s_mu, s_rs;
    int tid = threadIdx.x;
    int b = blockIdx.x >> 6;
    int p0 = (blockIdx.x & 63) << 6;
    int warp = tid >> 5, lane = tid & 31;
    int g = lane >> 2, t4 = lane & 3;

    float* ysh = pool;
    float* Wsh = pool + 64 * 128;

    if (tid < 32) {
        float ss = g_part[(b * 32 + tid) * 2];
        float sq = g_part[(b * 32 + tid) * 2 + 1];
        #pragma unroll
        for (int o = 16; o > 0; o >>= 1) {
            ss += __shfl_xor_sync(0xffffffffu, ss, o);
            sq += __shfl_xor_sync(0xffffffffu, sq, o);
        }
        if (tid == 0) {
            const float inv = 1.f / 524288.f;
            float mu = ss * inv;
            s_mu = mu;
            s_rs = rsqrtf(sq * inv - mu * mu + 1e-5f);
        }
    }
    {
        const float4* wsrc = (const float4*)g_FC1swz;
        float4* wdst = (float4*)Wsh;
        #pragma unroll
        for (int i = 0; i < 8; i++) wdst[i * 256 + tid] = wsrc[i * 256 + tid];
    }
    __syncthreads();
    float mu = s_mu, rs = s_rs;

    #pragma unroll
    for (int i = 0; i < 32; i++) {
        int lin = i * 256 + tid;
        int pix = lin >> 7, kk = lin & 127;
        size_t gi = ((size_t)b * NPIX + p0 + pix) * HID + kk;
        int ii = (p0 + pix) * HID + kk;
        float y = (g_hd[gi] - mu) * rs * nw[ii] + nb[ii];
        int half = kk >> 6, kc = kk & 63;
        ysh[pix * 128 + half * 64 + swz_pos(kc, pix & 1)] = __uint_as_float(f2tf32(y));
    }
    __syncthreads();

    {
        int pixBase = (warp & 1) * 32;
        int oBase = (warp >> 1) * 16;

        float acc[2][2][4];
        #pragma unroll
        for (int m = 0; m < 2; m++)
            #pragma unroll
            for (int n = 0; n < 2; n++)
                #pragma unroll
                for (int j = 0; j < 4; j++) acc[m][n][j] = 0.f;

        #pragma unroll
        for (int half = 0; half < 2; half++) {
            #pragma unroll
            for (int j = 0; j < 4; j++) {
                int pibase = t4 * 4 + ((j + t4) & 3);
                float4 av[4];
                #pragma unroll
                for (int r = 0; r < 4; r++) {
                    int pr = pixBase + r * 8 + g;
                    av[r] = *(const float4*)&ysh[pr * 128 + half * 64 + ((pibase ^ (pr & 1)) << 2)];
                }
                uint32_t aH0m0[4] = {__float_as_uint(av[0].x), __float_as_uint(av[1].x),
                                     __float_as_uint(av[0].y), __float_as_uint(av[1].y)};
                uint32_t aH1m0[4] = {__float_as_uint(av[0].z), __float_as_uint(av[1].z),
                                     __float_as_uint(av[0].w), __float_as_uint(av[1].w)};
                uint32_t aH0m1[4] = {__float_as_uint(av[2].x), __float_as_uint(av[3].x),
                                     __float_as_uint(av[2].y), __float_as_uint(av[3].y)};
                uint32_t aH1m1[4] = {__float_as_uint(av[2].z), __float_as_uint(av[3].z),
                                     __float_as_uint(av[2].w), __float_as_uint(av[3].w)};
                #pragma unroll
                for (int n = 0; n < 2; n++) {
                    int o = oBase + n * 8 + g;
                    float4 bv = *(const float4*)&Wsh[o * 128 + half * 64 + ((pibase ^ (o & 1)) << 2)];
                    uint32_t b0 = __float_as_uint(bv.x), b1 = __float_as_uint(bv.y);
                    uint32_t b2 = __float_as_uint(bv.z), b3 = __float_as_uint(bv.w);
                    mma_tf32(acc[0][n], aH0m0, b0, b1);
                    mma_tf32(acc[0][n], aH1m0, b2, b3);
                    mma_tf32(acc[1][n], aH0m1, b0, b1);
                    mma_tf32(acc[1][n], aH1m1, b2, b3);
                }
            }
        }

        int mode = g_maskmode;
        #pragma unroll
        for (int m = 0; m < 2; m++) {
            int p_lo = pixBase + m * 16 + g;
            int p_hi = p_lo + 8;
            size_t gplo = (size_t)b * NPIX + p0 + p_lo;
            size_t gphi = (size_t)b * NPIX + p0 + p_hi;
            size_t milo = (size_t)s * 32768 + gplo;
            size_t mihi = (size_t)s * 32768 + gphi;
            float mvlo, mvhi;
            if (mode) {
                mvlo = ((const unsigned char*)mask)[milo] ? 1.f : 0.f;
                mvhi = ((const unsigned char*)mask)[mihi] ? 1.f : 0.f;
            } else {
                mvlo = ((const unsigned int*)mask)[milo] ? 1.f : 0.f;
                mvhi = ((const unsigned int*)mask)[mihi] ? 1.f : 0.f;
            }
            #pragma unroll
            for (int n = 0; n < 2; n++) {
                int col = oBase + n * 8 + 2 * t4;
                float2 x0 = *(const float2*)&xin[gplo * CCH + col];
                float2 x1 = *(const float2*)&xin[gphi * CCH + col];
                float2 o0 = make_float2(x0.x + acc[m][n][0] * mvlo, x0.y + acc[m][n][1] * mvlo);
                float2 o1 = make_float2(x1.x + acc[m][n][2] * mvhi, x1.y + acc[m][n][3] * mvhi);
                *(float2*)&xout[gplo * CCH + col] = o0;
                *(float2*)&xout[gphi * CCH + col] = o1;
                *(float2*)&xsh[p_lo * 64 + col] = o0;
                *(float2*)&xsh[p_hi * 64 + col] = o1;
            }
        }
    }
    __syncthreads();

    float* ysh2 = pool;
    float* WshQ = pool + 64 * 64;

    #pragma unroll
    for (int k = 0; k < 8; k++) {
        int pix = warp * 8 + k;
        float v0 = xsh[pix * 64 + lane], v1 = xsh[pix * 64 + lane + 32];
        float ss = v0 + v1, sq = v0 * v0 + v1 * v1;
        #pragma unroll
        for (int o = 16; o > 0; o >>= 1) {
            ss += __shfl_xor_sync(0xffffffffu, ss, o);
            sq += __shfl_xor_sync(0xffffffffu, sq, o);
        }
        float mu2 = ss * (1.f / 64.f);
        float rsg = rsqrtf(sq * (1.f / 64.f) - mu2 * mu2 + 1e-5f);
        float y0 = (v0 - mu2) * rsg * lw[lane] + lb[lane];
        float y1 = (v1 - mu2) * rsg * lw[lane + 32] + lb[lane + 32];
        ysh2[pix * 64 + swz_pos(lane, pix & 1)] = __uint_as_float(f2tf32(y0));
        ysh2[pix * 64 + swz_pos(lane + 32, pix & 1)] = __uint_as_float(f2tf32(y1));
    }
    {
        const float4* wsrc = (const float4*)g_QKVswz;
        float4* wdst = (float4*)WshQ;
        #pragma unroll
        for (int i = 0; i < 12; i++) wdst[i * 256 + tid] = wsrc[i * 256 + tid];
    }
    __syncthreads();

    {
        int pixBase = (warp & 1) * 32;
        int oBase = (warp >> 1) * 48;

        float acc[2][6][4];
        #pragma unroll
        for (int m = 0; m < 2; m++)
            #pragma unroll
            for (int n = 0; n < 6; n++)
                #pragma unroll
                for (int j = 0; j < 4; j++) acc[m][n][j] = 0.f;

        #pragma unroll
        for (int j = 0; j < 4; j++) {
            int pibase = t4 * 4 + ((j + t4) & 3);
            float4 av[4];
            #pragma unroll
            for (int r = 0; r < 4; r++) {
                int pr = pixBase + r * 8 + g;
                av[r] = *(const float4*)&ysh2[pr * 64 + ((pibase ^ (pr & 1)) << 2)];
            }
            uint32_t aH0m0[4] = {__float_as_uint(av[0].x), __float_as_uint(av[1].x),
                                 __float_as_uint(av[0].y), __float_as_uint(av[1].y)};
            uint32_t aH1m0[4] = {__float_as_uint(av[0].z), __float_as_uint(av[1].z),
                                 __float_as_uint(av[0].w), __float_as_uint(av[1].w)};
            uint32_t aH0m1[4] = {__float_as_uint(av[2].x), __float_as_uint(av[3].x),
                                 __float_as_uint(av[2].y), __float_as_uint(av[3].y)};
            uint32_t aH1m1[4] = {__float_as_uint(av[2].z), __float_as_uint(av[3].z),
                                 __float_as_uint(av[2].w), __float_as_uint(av[3].w)};
            #pragma unroll
            for (int n = 0; n < 6; n++) {
                int o = oBase + n * 8 + g;
                float4 bv = *(const float4*)&WshQ[o * 64 + ((pibase ^ (o & 1)) << 2)];
                uint32_t b0 = __float_as_uint(bv.x), b1 = __float_as_uint(bv.y);
                uint32_t b2 = __float_as_uint(bv.z), b3 = __float_as_uint(bv.w);
                mma_tf32(acc[0][n], aH0m0, b0, b1);
                mma_tf32(acc[0][n], aH1m0, b2, b3);
                mma_tf32(acc[1][n], aH0m1, b0, b1);
                mma_tf32(acc[1][n], aH1m1, b2, b3);
            }
        }

        #pragma unroll
        for (int m = 0; m < 2; m++) {
            int p_lo = pixBase + m * 16 + g;
            int p_hi = p_lo + 8;
            size_t gplo = (size_t)b * NPIX + p0 + p_lo;
            size_t gphi = (size_t)b * NPIX + p0 + p_hi;
            #pragma unroll
            for (int n = 0; n < 6; n++) {
                int col = oBase + n * 8 + 2 * t4;
                int region = col >> 6;
                int c = col & 63;
                float* dst = (region == 0) ? g_q : (region == 1) ? g_k : g_v;
                *(float2*)&dst[gplo * CCH + c] = make_float2(acc[m][n][0], acc[m][n][1]);
                *(float2*)&dst[gphi * CCH + c] = make_float2(acc[m][n][2], acc[m][n][3]);
            }
        }
    }
}

// ---------------- fused attn + out-proj + ff with MMA GEMMs: 32 px per block ----------------
// smem floats: kv[7808] (ksh/vsh; wshp 64*66=4224 overlays) + oshp[2112] + tsh[2112]
//              + yshp[2112] + hshp[2112]  => 16256 floats = 65 KB
#define AF_SMEM_BYTES (16256 * 4)

__global__ void __launch_bounds__(128) k_attn_ff(const float* __restrict__ xn,
                                                 const float* __restrict__ xprev,
                                                 const float* __restrict__ outb,
                                                 const float* __restrict__ lw2,
                                                 const float* __restrict__ lb2,
                                                 const float* __restrict__ b1,
                                                 const float* __restrict__ b2,
                                                 float* __restrict__ xout) {
    extern __shared__ float sm[];
    float* ksh = sm;                  // [64ch][61pos]
    float* vsh = sm + 3904;
    float* wshp = sm;                 // overlays kv region for weights [64][66]
    float* oshp = sm + 7808;          // [32][66] pair-interleaved tf32 attn output
    float* tsh = oshp + 2112;         // [32][66] fp32 t values
    float* yshp = tsh + 2112;         // [32][66] pair-interleaved tf32 LN2 output
    float* hshp = yshp + 2112;        // [32][66] pair-interleaved tf32 GELU output
    int tid = threadIdx.x;
    int b = blockIdx.x >> 7;
    int tile = blockIdx.x & 127;
    int tx0 = (tile & 7) << 3;
    int ty0 = (tile >> 3) << 2;
    int warp = tid >> 5, lane = tid & 31;
    int g = lane >> 2, t4 = lane & 3;
    int mw = warp & 1, nw = warp >> 1;

    // phase 0: k/v halo
    #pragma unroll
    for (int i = 0; i < 30; i++) {
        int lin = tid + i * 128;
        int pos = lin >> 6, ch = lin & 63;
        int hy = pos / 10, hx = pos - hy * 10;
        int gy = ty0 + hy - 1, gx = tx0 + hx - 1;
        float kv = 0.f, vv = 0.f;
        if ((unsigned)gy < 64u && (unsigned)gx < 64u) {
            size_t a = ((size_t)b * NPIX + gy * 64 + gx) * CCH + ch;
            kv = g_k[a]; vv = g_v[a];
        }
        ksh[ch * 61 + pos] = kv;
        vsh[ch * 61 + pos] = vv;
    }
    __syncthreads();

    // phase 1: attention (warp = head, lane = pixel), store pair-interleaved tf32
    {
        int head = warp, lp = lane;
        int py = lp >> 3, px = lp & 7;
        int gy = ty0 + py, gx = tx0 + px;
        size_t qbase = ((size_t)b * NPIX + gy * 64 + gx) * CCH + head * 16;
        float q[16];
        #pragma unroll
        for (int i = 0; i < 4; i++) {
            float4 t4v = *(const float4*)&g_q[qbase + i * 4];
            q[i * 4] = t4v.x; q[i * 4 + 1] = t4v.y; q[i * 4 + 2] = t4v.z; q[i * 4 + 3] = t4v.w;
        }
        float lg[9];
        #pragma unroll
        for (int t = 0; t < 9; t++) {
            int pos = (py + t / 3) * 10 + px + t % 3;
            float d = 0.f;
            #pragma unroll
            for (int i = 0; i < 16; i++) d = fmaf(q[i], ksh[(head * 16 + i) * 61 + pos], d);
            lg[t] = d * ATT_SCALE;
        }
        float m = lg[0];
        #pragma unroll
        for (int t = 1; t < 9; t++) m = fmaxf(m, lg[t]);
        float e[9], ssum = 0.f;
        #pragma unroll
        for (int t = 0; t < 9; t++) { e[t] = __expf(lg[t] - m); ssum += e[t]; }
        float inv = 1.f / ssum;
        float o[16] = {};
        #pragma unroll
        for (int t = 0; t < 9; t++) {
            int pos = (py + t / 3) * 10 + px + t % 3;
            float a = e[t] * inv;
            #pragma unroll
            for (int i = 0; i < 16; i++) o[i] = fmaf(a, vsh[(head * 16 + i) * 61 + pos], o[i]);
        }
        #pragma unroll
        for (int i = 0; i < 16; i++)
            oshp[lp * 66 + pairpos(head * 16 + i)] = __uint_as_float(f2tf32(o[i]));
    }
    __syncthreads();

    // phase 2: stage out-proj weights (overlays kv region — attention reads are done)
    {
        const float4* wsrc = (const float4*)g_OUTp;
        float4* wdst = (float4*)wshp;
        #pragma unroll
        for (int i = 0; i < 9; i++) {
            int idx = i * 128 + tid;
            if (idx < 1056) wdst[idx] = wsrc[idx];
        }
    }
    __syncthreads();

    // phase 3: out-proj MMA + bias + residual -> tsh (fp32)
    {
        float acc[4][4] = {{0}};
        gemm32_66(oshp, wshp, mw, nw, g, t4, acc);
        int r0 = mw * 16 + g, r1 = r0 + 8;
        int gp0 = (ty0 + (r0 >> 3)) * 64 + tx0 + (r0 & 7);
        int gp1 = (ty0 + (r1 >> 3)) * 64 + tx0 + (r1 & 7);
        size_t b0a = ((size_t)b * NPIX + gp0) * CCH;
        size_t b1a = ((size_t)b * NPIX + gp1) * CCH;
        #pragma unroll
        for (int n = 0; n < 4; n++) {
            int col = nw * 32 + n * 8 + 2 * t4;
            tsh[r0 * 66 + col]     = acc[n][0] + outb[col]     + xn[b0a + col];
            tsh[r0 * 66 + col + 1] = acc[n][1] + outb[col + 1] + xn[b0a + col + 1];
            tsh[r1 * 66 + col]     = acc[n][2] + outb[col]     + xn[b1a + col];
            tsh[r1 * 66 + col + 1] = acc[n][3] + outb[col + 1] + xn[b1a + col + 1];
        }
    }
    __syncthreads();

    // phase 4: LN2 (warp handles 8 px) -> yshp ; stage ff1 weights
    #pragma unroll
    for (int k = 0; k < 8; k++) {
        int pix = warp * 8 + k;
        float v0 = tsh[pix * 66 + lane], v1 = tsh[pix * 66 + lane + 32];
        float ss = v0 + v1, sq = v0 * v0 + v1 * v1;
        #pragma unroll
        for (int o = 16; o > 0; o >>= 1) {
            ss += __shfl_xor_sync(0xffffffffu, ss, o);
            sq += __shfl_xor_sync(0xffffffffu, sq, o);
        }
        float mu = ss * (1.f / 64.f);
        float rsg = rsqrtf(sq * (1.f / 64.f) - mu * mu + 1e-5f);
        float y0 = (v0 - mu) * rsg * lw2[lane] + lb2[lane];
        float y1 = (v1 - mu) * rsg * lw2[lane + 32] + lb2[lane + 32];
        yshp[pix * 66 + pairpos(lane)] = __uint_as_float(f2tf32(y0));
        yshp[pix * 66 + pairpos(lane + 32)] = __uint_as_float(f2tf32(y1));
    }
    {
        const float4* wsrc = (const float4*)g_FF1p;
        float4* wdst = (float4*)wshp;
        #pragma unroll
        for (int i = 0; i < 9; i++) {
            int idx = i * 128 + tid;
            if (idx < 1056) wdst[idx] = wsrc[idx];
        }
    }
    __syncthreads();

    // phase 5: ff1 MMA + bias + GELU -> hshp
    {
        float acc[4][4] = {{0}};
        gemm32_66(yshp, wshp, mw, nw, g, t4, acc);
        int r0 = mw * 16 + g, r1 = r0 + 8;
        #pragma unroll
        for (int n = 0; n < 4; n++) {
            int col = nw * 32 + n * 8 + 2 * t4;
            float bb0 = b1[col], bb1 = b1[col + 1];
            float h0 = acc[n][0] + bb0, h1 = acc[n][1] + bb1;
            float h2 = acc[n][2] + bb0, h3 = acc[n][3] + bb1;
            h0 = 0.5f * h0 * (1.f + erff(h0 * 0.70710678118654752f));
            h1 = 0.5f * h1 * (1.f + erff(h1 * 0.70710678118654752f));
            h2 = 0.5f * h2 * (1.f + erff(h2 * 0.70710678118654752f));
            h3 = 0.5f * h3 * (1.f + erff(h3 * 0.70710678118654752f));
            hshp[r0 * 66 + pairpos(col)]     = __uint_as_float(f2tf32(h0));
            hshp[r0 * 66 + pairpos(col + 1)] = __uint_as_float(f2tf32(h1));
            hshp[r1 * 66 + pairpos(col)]     = __uint_as_float(f2tf32(h2));
            hshp[r1 * 66 + pairpos(col + 1)] = __uint_as_float(f2tf32(h3));
        }
    }
    __syncthreads();

    // stage ff2 weights
    {
        const float4* wsrc = (const float4*)g_FF2p;
        float4* wdst = (float4*)wshp;
        #pragma unroll
        for (int i = 0; i < 9; i++) {
            int idx = i * 128 + tid;
            if (idx < 1056) wdst[idx] = wsrc[idx];
        }
    }
    __syncthreads();

    // phase 6: ff2 MMA + bias + residual + ch0 restore -> global
    {
        float acc[4][4] = {{0}};
        gemm32_66(hshp, wshp, mw, nw, g, t4, acc);
        int r0 = mw * 16 + g, r1 = r0 + 8;
        int gp0 = (ty0 + (r0 >> 3)) * 64 + tx0 + (r0 & 7);
        int gp1 = (ty0 + (r1 >> 3)) * 64 + tx0 + (r1 & 7);
        size_t b0a = ((size_t)b * NPIX + gp0) * CCH;
        size_t b1a = ((size_t)b * NPIX + gp1) * CCH;
        #pragma unroll
        for (int n = 0; n < 4; n++) {
            int col = nw * 32 + n * 8 + 2 * t4;
            float v00 = acc[n][0] + b2[col]     + tsh[r0 * 66 + col];
            float v01 = acc[n][1] + b2[col + 1] + tsh[r0 * 66 + col + 1];
            float v10 = acc[n][2] + b2[col]     + tsh[r1 * 66 + col];
            float v11 = acc[n][3] + b2[col + 1] + tsh[r1 * 66 + col + 1];
            if (col == 0) { v00 = xprev[b0a]; v10 = xprev[b1a]; }
            xout[b0a + col]     = v00;
            xout[b0a + col + 1] = v01;
            xout[b1a + col]     = v10;
            xout[b1a + col + 1] = v11;
        }
    }
}

extern "C" void kernel_launch(void* const* d_in, const int* in_sizes, int n_in,
                              void* d_out, int out_size) {
    const float* x = (const float*)d_in[0];
    const void* masks = d_in[1];
    const float* p0_w = (const float*)d_in[2];
    const float* p0_b = (const float*)d_in[3];
    const float* p1_w = (const float*)d_in[4];
    const float* p1_b = (const float*)d_in[5];
    const float* fc0_w = (const float*)d_in[6];
    const float* fc0_b = (const float*)d_in[7];
    const float* fc1_w = (const float*)d_in[8];
    const float* n0w = (const float*)d_in[9];
    const float* n0b = (const float*)d_in[10];
    const float* ln1w = (const float*)d_in[11];
    const float* ln1b = (const float*)d_in[12];
    const float* qkvw = (const float*)d_in[13];
    const float* outw = (const float*)d_in[14];
    const float* outb = (const float*)d_in[15];
    const float* ln2w = (const float*)d_in[16];
    const float* ln2b = (const float*)d_in[17];
    const float* ff1w = (const float*)d_in[18];
    const float* ff1b = (const float*)d_in[19];
    const float* ff2w = (const float*)d_in[20];
    const float* ff2b = (const float*)d_in[21];
    float* out = (float*)d_out;

    cudaFuncSetAttribute(k_conv_mma, cudaFuncAttributeMaxDynamicSharedMemorySize, CONV_SMEM_BYTES);
    cudaFuncSetAttribute(k_fc1qkv, cudaFuncAttributeMaxDynamicSharedMemorySize, FQ_SMEM_BYTES);
    cudaFuncSetAttribute(k_attn_ff, cudaFuncAttributeMaxDynamicSharedMemorySize, AF_SMEM_BYTES);

    k_fold<<<288, 256>>>(fc0_w, fc0_b, p0_w, p0_b, p1_w, p1_b);
    k_prepw<<<48, 256>>>(qkvw, fc1_w, outw, ff1w, ff2w);
    k_maskdetect<<<1, 1024>>>((const unsigned char*)masks, 6 * BATCH * NPIX);

    void* sym = nullptr;
    cudaGetSymbolAddress(&sym, g_xbuf);
    float* buf0 = (float*)sym;
    float* buf1 = buf0 + BATCH * NPIX * CCH;

    const float* cur = x;
    for (int s = 0; s < 6; s++) {
        float* stage = (s & 1) ? buf1 : buf0;
        float* nxt = (s == 5) ? out : stage;
        k_conv_mma<<<256, 256, CONV_SMEM_BYTES>>>(cur);
        k_fc1qkv<<<512, 256, FQ_SMEM_BYTES>>>(cur, n0w, n0b, masks, s, stage, ln1w, ln1b);
        k_attn_ff<<<1024, 128, AF_SMEM_BYTES>>>(stage, cur, outb, ln2w, ln2b,
                                                ff1b, ff2b, nxt);
        cur = nxt;
    }
}